// round 4
// baseline (speedup 1.0000x reference)
#include <cuda_runtime.h>
#include <math.h>

#define BB 4
#define SS 2048
#define DM 1024
#define NH 16
#define DK 64
#define MTOT (BB*SS)

// scratch (device globals; allocation-free at launch time)
__device__ float g_Q[(size_t)MTOT*DM];
__device__ float g_K[(size_t)MTOT*DM];
__device__ float g_V[(size_t)MTOT*DM];
__device__ float g_C[(size_t)MTOT*DM];

// ---------------------------------------------------------------------------
// helpers
// ---------------------------------------------------------------------------
__device__ __forceinline__ unsigned f2tf32u(float x) {
    unsigned y;
    asm("cvt.rna.tf32.f32 %0, %1;" : "=r"(y) : "f"(x));
    return y;
}
__device__ __forceinline__ float f2tf32f(float x) { return __uint_as_float(f2tf32u(x)); }

__device__ __forceinline__ void mma_tf32(float c[4],
                                         unsigned a0, unsigned a1, unsigned a2, unsigned a3,
                                         unsigned b0, unsigned b1) {
    asm volatile(
        "mma.sync.aligned.m16n8k8.row.col.f32.tf32.tf32.f32 "
        "{%0,%1,%2,%3},{%4,%5,%6,%7},{%8,%9},{%0,%1,%2,%3};"
        : "+f"(c[0]), "+f"(c[1]), "+f"(c[2]), "+f"(c[3])
        : "r"(a0), "r"(a1), "r"(a2), "r"(a3), "r"(b0), "r"(b1));
}

__device__ __forceinline__ void cp16(void* dst_smem, const void* src_gmem) {
    unsigned s = (unsigned)__cvta_generic_to_shared(dst_smem);
    asm volatile("cp.async.cg.shared.global [%0], [%1], 16;" :: "r"(s), "l"(src_gmem));
}
__device__ __forceinline__ void cp_commit() { asm volatile("cp.async.commit_group;"); }
template<int N> __device__ __forceinline__ void cp_wait() {
    asm volatile("cp.async.wait_group %0;" :: "n"(N));
}

// log2(10000)/32
#define ROPE_L2 0.41524101186f

// ---------------------------------------------------------------------------
// TF32 GEMM v3: C[M,N] = A[M,K] * W[K,N]. BM=BN=128, BK=16, 128 threads =
// 4 warps (2x2), warp tile 64x64 (4 m-tiles x 8 n-tiles of m16n8k8).
// cp.async double-buffered. Optional fused RoPE; optional tf32-rounded store.
// ---------------------------------------------------------------------------
template<bool ROPE, bool ROUND>
__global__ __launch_bounds__(128) void gemm_tf32_v3(const float* __restrict__ A,
                                                    const float* __restrict__ W,
                                                    float* __restrict__ C) {
    __shared__ float As[2][128][20];   // [m][k], pad 20 -> conflict-free frags
    __shared__ float Bs[2][16][136];   // [k][n], pad 136

    const int tid  = threadIdx.x;
    const int wid  = tid >> 5;
    const int lane = tid & 31;
    const int g    = lane >> 2;
    const int tig  = lane & 3;
    const int rw   = wid >> 1;       // warp m index 0..1
    const int cw   = wid & 1;        // warp n index 0..1
    const int m0   = blockIdx.y * 128;
    const int n0   = blockIdx.x * 128;

    const int lr = tid;               // A row 0..127 (16 floats each)
    const int wr = tid >> 3;          // B row 0..15
    const int wc = (tid & 7) * 16;    // B col base (16 floats each)

    float acc[4][8][4];
    #pragma unroll
    for (int i = 0; i < 4; i++)
        #pragma unroll
        for (int j = 0; j < 8; j++)
            #pragma unroll
            for (int l = 0; l < 4; l++) acc[i][j][l] = 0.0f;

    const float* asrc = A + (size_t)(m0 + lr) * DM;
    const float* bsrc = W + (size_t)wr * DM + n0 + wc;

    // prefetch tile 0
    #pragma unroll
    for (int j = 0; j < 4; j++) {
        cp16(&As[0][lr][j * 4], asrc + j * 4);
        cp16(&Bs[0][wr][wc + j * 4], bsrc + j * 4);
    }
    cp_commit();

    const int NT = DM / 16;
    for (int t = 0; t < NT; t++) {
        const int buf = t & 1;
        if (t + 1 < NT) {
            const float* a2 = asrc + (t + 1) * 16;
            const float* b2 = bsrc + (size_t)(t + 1) * 16 * DM;
            #pragma unroll
            for (int j = 0; j < 4; j++) {
                cp16(&As[buf ^ 1][lr][j * 4], a2 + j * 4);
                cp16(&Bs[buf ^ 1][wr][wc + j * 4], b2 + j * 4);
            }
            cp_commit();
            cp_wait<1>();
        } else {
            cp_wait<0>();
        }
        __syncthreads();

        #pragma unroll
        for (int ks = 0; ks < 16; ks += 8) {
            unsigned a[4][4];
            #pragma unroll
            for (int mt = 0; mt < 4; mt++) {
                const int r = rw * 64 + mt * 16;
                a[mt][0] = f2tf32u(As[buf][r + g][ks + tig]);
                a[mt][1] = f2tf32u(As[buf][r + g + 8][ks + tig]);
                a[mt][2] = f2tf32u(As[buf][r + g][ks + tig + 4]);
                a[mt][3] = f2tf32u(As[buf][r + g + 8][ks + tig + 4]);
            }
            unsigned b[8][2];
            #pragma unroll
            for (int nt = 0; nt < 8; nt++) {
                const int n = cw * 64 + nt * 8;
                b[nt][0] = f2tf32u(Bs[buf][ks + tig][n + g]);
                b[nt][1] = f2tf32u(Bs[buf][ks + tig + 4][n + g]);
            }
            #pragma unroll
            for (int mt = 0; mt < 4; mt++)
                #pragma unroll
                for (int nt = 0; nt < 8; nt++)
                    mma_tf32(acc[mt][nt], a[mt][0], a[mt][1], a[mt][2], a[mt][3],
                             b[nt][0], b[nt][1]);
        }
        __syncthreads();
    }

    // epilogue: optional fused RoPE, optional tf32 rounding of the stored value
    #pragma unroll
    for (int mt = 0; mt < 4; mt++) {
        const int r = m0 + rw * 64 + mt * 16 + g;
        const int pos0 = r & (SS - 1);
        const int pos8 = (r + 8) & (SS - 1);
        #pragma unroll
        for (int nt = 0; nt < 8; nt++) {
            const int c = n0 + cw * 64 + nt * 8 + 2 * tig;
            float y0 = acc[mt][nt][0], y1 = acc[mt][nt][1];
            float y2 = acc[mt][nt][2], y3 = acc[mt][nt][3];
            if (ROPE) {
                const int i = (c & 63) >> 1;
                const float inv = exp2f(-(float)i * ROPE_L2);
                float s0, c0, s8, c8;
                sincosf((float)pos0 * inv, &s0, &c0);
                sincosf((float)pos8 * inv, &s8, &c8);
                float x1 = y0, x2 = y1;
                y0 = x1 * c0 - x2 * s0;
                y1 = x1 * s0 + x2 * c0;
                x1 = y2; x2 = y3;
                y2 = x1 * c8 - x2 * s8;
                y3 = x1 * s8 + x2 * c8;
            }
            if (ROUND) {
                y0 = f2tf32f(y0); y1 = f2tf32f(y1);
                y2 = f2tf32f(y2); y3 = f2tf32f(y3);
            }
            *(float2*)&C[(size_t)r * DM + c]       = make_float2(y0, y1);
            *(float2*)&C[(size_t)(r + 8) * DM + c] = make_float2(y2, y3);
        }
    }
}

// ---------------------------------------------------------------------------
// Flash attention, tf32. BM=128 q rows, BN=64 keys/iter, DK=64.
// 256 threads = 8 warps, each warp owns 16 q rows; Q fragments in registers;
// K/V arrive PRE-ROUNDED to tf32 (projection epilogue), so no cvt in loop.
// ---------------------------------------------------------------------------
__global__ __launch_bounds__(256, 2) void flash_tf32_v3(const float* __restrict__ Q,
                                                        const float* __restrict__ K,
                                                        const float* __restrict__ V,
                                                        float* __restrict__ O) {
    extern __shared__ float sm[];
    float* Ks = sm;                    // [2][64][68]
    float* Vs = Ks + 2 * 64 * 68;      // [2][64][72]
    float* Ps = Vs + 2 * 64 * 72;      // [128][68]

    const int tid  = threadIdx.x;
    const int wid  = tid >> 5;
    const int lane = tid & 31;
    const int g    = lane >> 2;
    const int tig  = lane & 3;
    const int h    = blockIdx.y;
    const int b    = blockIdx.z;
    const int q0   = wid * 16;
    const size_t qbase = ((size_t)b * SS + blockIdx.x * 128) * DM + h * DK;
    const size_t kvbase = (size_t)b * SS * DM + h * DK;

    // Q fragments straight from gmem (scaled by 1/sqrt(dk), tf32-rounded once)
    unsigned qf[8][4];
    {
        const float* q_r0 = Q + qbase + (size_t)(q0 + g) * DM;
        const float* q_r8 = Q + qbase + (size_t)(q0 + g + 8) * DM;
        #pragma unroll
        for (int k8 = 0; k8 < 8; k8++) {
            const int cc = k8 * 8 + tig;
            qf[k8][0] = f2tf32u(0.125f * __ldg(q_r0 + cc));
            qf[k8][1] = f2tf32u(0.125f * __ldg(q_r8 + cc));
            qf[k8][2] = f2tf32u(0.125f * __ldg(q_r0 + cc + 4));
            qf[k8][3] = f2tf32u(0.125f * __ldg(q_r8 + cc + 4));
        }
    }

    const int pr = tid >> 2;            // row 0..63
    const int pc = (tid & 3) * 16;      // col base
    auto kv_prefetch = [&](int kt, int buf) {
        const float* ksrc = K + kvbase + ((size_t)kt * 64 + pr) * DM + pc;
        const float* vsrc = V + kvbase + ((size_t)kt * 64 + pr) * DM + pc;
        float* kd = Ks + buf * 64 * 68 + pr * 68 + pc;
        float* vd = Vs + buf * 64 * 72 + pr * 72 + pc;
        #pragma unroll
        for (int j = 0; j < 4; j++) {
            cp16(kd + j * 4, ksrc + j * 4);
            cp16(vd + j * 4, vsrc + j * 4);
        }
        cp_commit();
    };

    kv_prefetch(0, 0);

    float o[8][4];
    #pragma unroll
    for (int nt = 0; nt < 8; nt++)
        #pragma unroll
        for (int j = 0; j < 4; j++) o[nt][j] = 0.0f;
    float mrow0 = -INFINITY, mrow1 = -INFINITY;
    float lrow0 = 0.0f, lrow1 = 0.0f;

    const int NKT = SS / 64;
    for (int kt = 0; kt < NKT; kt++) {
        const int buf = kt & 1;
        __syncthreads();
        if (kt + 1 < NKT) {
            kv_prefetch(kt + 1, buf ^ 1);
            cp_wait<1>();
        } else {
            cp_wait<0>();
        }
        __syncthreads();

        const float* KsB = Ks + buf * 64 * 68;
        const float* VsB = Vs + buf * 64 * 72;

        // S = (Q*scale) K^T
        float s[8][4];
        #pragma unroll
        for (int nt = 0; nt < 8; nt++)
            #pragma unroll
            for (int j = 0; j < 4; j++) s[nt][j] = 0.0f;

        #pragma unroll
        for (int k8 = 0; k8 < 8; k8++) {
            const int kk = k8 * 8;
            #pragma unroll
            for (int nt = 0; nt < 8; nt++) {
                unsigned b0 = __float_as_uint(KsB[(nt * 8 + g) * 68 + kk + tig]);
                unsigned b1 = __float_as_uint(KsB[(nt * 8 + g) * 68 + kk + tig + 4]);
                mma_tf32(s[nt], qf[k8][0], qf[k8][1], qf[k8][2], qf[k8][3], b0, b1);
            }
        }

        // online softmax
        float mx0 = -INFINITY, mx1 = -INFINITY;
        #pragma unroll
        for (int nt = 0; nt < 8; nt++) {
            mx0 = fmaxf(mx0, fmaxf(s[nt][0], s[nt][1]));
            mx1 = fmaxf(mx1, fmaxf(s[nt][2], s[nt][3]));
        }
        mx0 = fmaxf(mx0, __shfl_xor_sync(0xffffffffu, mx0, 1));
        mx0 = fmaxf(mx0, __shfl_xor_sync(0xffffffffu, mx0, 2));
        mx1 = fmaxf(mx1, __shfl_xor_sync(0xffffffffu, mx1, 1));
        mx1 = fmaxf(mx1, __shfl_xor_sync(0xffffffffu, mx1, 2));

        const float mn0 = fmaxf(mrow0, mx0);
        const float mn1 = fmaxf(mrow1, mx1);
        const float f0 = __expf(mrow0 - mn0);
        const float f1 = __expf(mrow1 - mn1);
        mrow0 = mn0; mrow1 = mn1;

        float sum0 = 0.0f, sum1 = 0.0f;
        #pragma unroll
        for (int nt = 0; nt < 8; nt++) {
            float p0 = __expf(s[nt][0] - mn0);
            float p1 = __expf(s[nt][1] - mn0);
            float p2 = __expf(s[nt][2] - mn1);
            float p3 = __expf(s[nt][3] - mn1);
            sum0 += p0 + p1;
            sum1 += p2 + p3;
            const int kc = nt * 8 + 2 * tig;
            *(float2*)&Ps[(q0 + g) * 68 + kc]     = make_float2(f2tf32f(p0), f2tf32f(p1));
            *(float2*)&Ps[(q0 + g + 8) * 68 + kc] = make_float2(f2tf32f(p2), f2tf32f(p3));
        }
        sum0 += __shfl_xor_sync(0xffffffffu, sum0, 1);
        sum0 += __shfl_xor_sync(0xffffffffu, sum0, 2);
        sum1 += __shfl_xor_sync(0xffffffffu, sum1, 1);
        sum1 += __shfl_xor_sync(0xffffffffu, sum1, 2);
        lrow0 = lrow0 * f0 + sum0;
        lrow1 = lrow1 * f1 + sum1;

        #pragma unroll
        for (int nt = 0; nt < 8; nt++) {
            o[nt][0] *= f0; o[nt][1] *= f0;
            o[nt][2] *= f1; o[nt][3] *= f1;
        }

        __syncwarp();

        // O += P V
        #pragma unroll
        for (int k8 = 0; k8 < 8; k8++) {
            const int kk = k8 * 8;
            unsigned a0 = __float_as_uint(Ps[(q0 + g) * 68 + kk + tig]);
            unsigned a1 = __float_as_uint(Ps[(q0 + g + 8) * 68 + kk + tig]);
            unsigned a2 = __float_as_uint(Ps[(q0 + g) * 68 + kk + tig + 4]);
            unsigned a3 = __float_as_uint(Ps[(q0 + g + 8) * 68 + kk + tig + 4]);
            #pragma unroll
            for (int nt = 0; nt < 8; nt++) {
                unsigned b0 = __float_as_uint(VsB[(kk + tig) * 72 + nt * 8 + g]);
                unsigned b1 = __float_as_uint(VsB[(kk + tig + 4) * 72 + nt * 8 + g]);
                mma_tf32(o[nt], a0, a1, a2, a3, b0, b1);
            }
        }
    }

    // normalize + write context
    const float inv0 = 1.0f / lrow0;
    const float inv1 = 1.0f / lrow1;
    #pragma unroll
    for (int nt = 0; nt < 8; nt++) {
        const int c = nt * 8 + 2 * tig;
        *(float2*)&O[qbase + (size_t)(q0 + g) * DM + c] =
            make_float2(o[nt][0] * inv0, o[nt][1] * inv0);
        *(float2*)&O[qbase + (size_t)(q0 + g + 8) * DM + c] =
            make_float2(o[nt][2] * inv1, o[nt][3] * inv1);
    }
}

// ---------------------------------------------------------------------------
extern "C" void kernel_launch(void* const* d_in, const int* in_sizes, int n_in,
                              void* d_out, int out_size) {
    const float* q  = (const float*)d_in[0];
    const float* k  = (const float*)d_in[1];
    const float* v  = (const float*)d_in[2];
    const float* Wq = (const float*)d_in[3];
    const float* Wk = (const float*)d_in[4];
    const float* Wv = (const float*)d_in[5];
    const float* Wo = (const float*)d_in[6];
    float* out = (float*)d_out;

    float *gQ, *gK, *gV, *gC;
    cudaGetSymbolAddress((void**)&gQ, g_Q);
    cudaGetSymbolAddress((void**)&gK, g_K);
    cudaGetSymbolAddress((void**)&gV, g_V);
    cudaGetSymbolAddress((void**)&gC, g_C);

    dim3 gGrid(DM / 128, MTOT / 128);

    // projections + fused RoPE on Q,K; K,V stored pre-rounded to tf32
    gemm_tf32_v3<true,  false><<<gGrid, 128>>>(q, Wq, gQ);
    gemm_tf32_v3<true,  true ><<<gGrid, 128>>>(k, Wk, gK);
    gemm_tf32_v3<false, true ><<<gGrid, 128>>>(v, Wv, gV);

    // flash attention
    const int smem = (2 * 64 * 68 + 2 * 64 * 72 + 128 * 68) * (int)sizeof(float);
    cudaFuncSetAttribute(flash_tf32_v3, cudaFuncAttributeMaxDynamicSharedMemorySize, smem);
    dim3 aGrid(SS / 128, NH, BB);
    flash_tf32_v3<<<aGrid, 256, smem>>>(gQ, gK, gV, gC);

    // output projection
    gemm_tf32_v3<false, false><<<gGrid, 128>>>(gC, Wo, out);
}

// round 5
// speedup vs baseline: 1.1082x; 1.1082x over previous
#include <cuda_runtime.h>
#include <math.h>

#define BB 4
#define SS 2048
#define DM 1024
#define NH 16
#define DK 64
#define MTOT (BB*SS)

// scratch (device globals; allocation-free at launch time)
__device__ float g_Q[(size_t)MTOT*DM];
__device__ float g_K[(size_t)MTOT*DM];
__device__ float g_V[(size_t)MTOT*DM];
__device__ float g_C[(size_t)MTOT*DM];

// ---------------------------------------------------------------------------
// helpers
// ---------------------------------------------------------------------------
__device__ __forceinline__ unsigned f2tf32u(float x) {
    unsigned y;
    asm("cvt.rna.tf32.f32 %0, %1;" : "=r"(y) : "f"(x));
    return y;
}
__device__ __forceinline__ float f2tf32f(float x) { return __uint_as_float(f2tf32u(x)); }

__device__ __forceinline__ void mma_tf32(float c[4],
                                         unsigned a0, unsigned a1, unsigned a2, unsigned a3,
                                         unsigned b0, unsigned b1) {
    asm volatile(
        "mma.sync.aligned.m16n8k8.row.col.f32.tf32.tf32.f32 "
        "{%0,%1,%2,%3},{%4,%5,%6,%7},{%8,%9},{%0,%1,%2,%3};"
        : "+f"(c[0]), "+f"(c[1]), "+f"(c[2]), "+f"(c[3])
        : "r"(a0), "r"(a1), "r"(a2), "r"(a3), "r"(b0), "r"(b1));
}

__device__ __forceinline__ void cp16(void* dst_smem, const void* src_gmem) {
    unsigned s = (unsigned)__cvta_generic_to_shared(dst_smem);
    asm volatile("cp.async.cg.shared.global [%0], [%1], 16;" :: "r"(s), "l"(src_gmem));
}
__device__ __forceinline__ void cp_commit() { asm volatile("cp.async.commit_group;"); }
template<int N> __device__ __forceinline__ void cp_wait() {
    asm volatile("cp.async.wait_group %0;" :: "n"(N));
}

// log2(10000)/32
#define ROPE_L2 0.41524101186f

// ---------------------------------------------------------------------------
// TF32 GEMM (v2 shape — measured good): BM=BN=128, BK=16, 256 thr = 8 warps
// (4x2), warp tile 32x64. cp.async double-buffered. Fused RoPE / tf32 ROUND.
// ---------------------------------------------------------------------------
template<bool ROPE, bool ROUND>
__global__ __launch_bounds__(256) void gemm_tf32_v2(const float* __restrict__ A,
                                                    const float* __restrict__ W,
                                                    float* __restrict__ C) {
    __shared__ float As[2][128][20];   // [m][k] padded
    __shared__ float Bs[2][16][136];   // [k][n] padded

    const int tid  = threadIdx.x;
    const int wid  = tid >> 5;
    const int lane = tid & 31;
    const int g    = lane >> 2;
    const int tig  = lane & 3;
    const int rw   = wid >> 1;
    const int cw   = wid & 1;
    const int m0   = blockIdx.y * 128;
    const int n0   = blockIdx.x * 128;

    const int lr = tid >> 1;          // A row 0..127
    const int lc = (tid & 1) * 8;     // A col base {0,8}
    const int wr = tid >> 4;          // B row 0..15
    const int wc = (tid & 15) * 8;    // B col base

    float acc[2][8][4];
    #pragma unroll
    for (int i = 0; i < 2; i++)
        #pragma unroll
        for (int j = 0; j < 8; j++)
            #pragma unroll
            for (int l = 0; l < 4; l++) acc[i][j][l] = 0.0f;

    const float* asrc = A + (size_t)(m0 + lr) * DM + lc;
    const float* bsrc = W + (size_t)wr * DM + n0 + wc;

    cp16(&As[0][lr][lc],     asrc);
    cp16(&As[0][lr][lc + 4], asrc + 4);
    cp16(&Bs[0][wr][wc],     bsrc);
    cp16(&Bs[0][wr][wc + 4], bsrc + 4);
    cp_commit();

    const int NT = DM / 16;
    for (int t = 0; t < NT; t++) {
        const int buf = t & 1;
        if (t + 1 < NT) {
            const float* a2 = asrc + (t + 1) * 16;
            const float* b2 = bsrc + (size_t)(t + 1) * 16 * DM;
            cp16(&As[buf ^ 1][lr][lc],     a2);
            cp16(&As[buf ^ 1][lr][lc + 4], a2 + 4);
            cp16(&Bs[buf ^ 1][wr][wc],     b2);
            cp16(&Bs[buf ^ 1][wr][wc + 4], b2 + 4);
            cp_commit();
            cp_wait<1>();
        } else {
            cp_wait<0>();
        }
        __syncthreads();

        #pragma unroll
        for (int ks = 0; ks < 16; ks += 8) {
            unsigned a[2][4];
            #pragma unroll
            for (int mt = 0; mt < 2; mt++) {
                const int r = rw * 32 + mt * 16;
                a[mt][0] = f2tf32u(As[buf][r + g][ks + tig]);
                a[mt][1] = f2tf32u(As[buf][r + g + 8][ks + tig]);
                a[mt][2] = f2tf32u(As[buf][r + g][ks + tig + 4]);
                a[mt][3] = f2tf32u(As[buf][r + g + 8][ks + tig + 4]);
            }
            unsigned b[8][2];
            #pragma unroll
            for (int nt = 0; nt < 8; nt++) {
                const int n = cw * 64 + nt * 8;
                b[nt][0] = f2tf32u(Bs[buf][ks + tig][n + g]);
                b[nt][1] = f2tf32u(Bs[buf][ks + tig + 4][n + g]);
            }
            #pragma unroll
            for (int mt = 0; mt < 2; mt++)
                #pragma unroll
                for (int nt = 0; nt < 8; nt++)
                    mma_tf32(acc[mt][nt], a[mt][0], a[mt][1], a[mt][2], a[mt][3],
                             b[nt][0], b[nt][1]);
        }
        __syncthreads();
    }

    #pragma unroll
    for (int mt = 0; mt < 2; mt++) {
        const int r = m0 + rw * 32 + mt * 16 + g;
        const int pos0 = r & (SS - 1);
        const int pos8 = (r + 8) & (SS - 1);
        #pragma unroll
        for (int nt = 0; nt < 8; nt++) {
            const int c = n0 + cw * 64 + nt * 8 + 2 * tig;
            float y0 = acc[mt][nt][0], y1 = acc[mt][nt][1];
            float y2 = acc[mt][nt][2], y3 = acc[mt][nt][3];
            if (ROPE) {
                const int i = (c & 63) >> 1;
                const float inv = exp2f(-(float)i * ROPE_L2);
                float s0, c0, s8, c8;
                sincosf((float)pos0 * inv, &s0, &c0);
                sincosf((float)pos8 * inv, &s8, &c8);
                float x1 = y0, x2 = y1;
                y0 = x1 * c0 - x2 * s0;
                y1 = x1 * s0 + x2 * c0;
                x1 = y2; x2 = y3;
                y2 = x1 * c8 - x2 * s8;
                y3 = x1 * s8 + x2 * c8;
            }
            if (ROUND) {
                y0 = f2tf32f(y0); y1 = f2tf32f(y1);
                y2 = f2tf32f(y2); y3 = f2tf32f(y3);
            }
            *(float2*)&C[(size_t)r * DM + c]       = make_float2(y0, y1);
            *(float2*)&C[(size_t)(r + 8) * DM + c] = make_float2(y2, y3);
        }
    }
}

// ---------------------------------------------------------------------------
// Flash attention v4, tf32. BM=128 q rows, BN=64 keys/iter, DK=64.
// 128 threads = 4 warps, each warp owns 32 q rows (2 m16 tiles) so K/V
// b-fragments are reused across 2 MMAs. Q frags in registers. K/V arrive
// pre-rounded tf32 (projection epilogue) -> no cvt in mainloop.
// ---------------------------------------------------------------------------
__global__ __launch_bounds__(128, 2) void flash_tf32_v4(const float* __restrict__ Q,
                                                        const float* __restrict__ K,
                                                        const float* __restrict__ V,
                                                        float* __restrict__ O) {
    extern __shared__ float sm[];
    float* Ks = sm;                    // [2][64][68]
    float* Vs = Ks + 2 * 64 * 68;      // [2][64][72]
    float* Ps = Vs + 2 * 64 * 72;      // [128][68]

    const int tid  = threadIdx.x;
    const int wid  = tid >> 5;
    const int lane = tid & 31;
    const int g    = lane >> 2;
    const int tig  = lane & 3;
    const int h    = blockIdx.y;
    const int b    = blockIdx.z;
    const int q0   = wid * 32;
    const size_t qbase = ((size_t)b * SS + blockIdx.x * 128) * DM + h * DK;
    const size_t kvbase = (size_t)b * SS * DM + h * DK;

    // Q fragments (scaled by 1/8, tf32-rounded once): 2 m-tiles x 8 k8 x 4
    unsigned qf[2][8][4];
    #pragma unroll
    for (int mt = 0; mt < 2; mt++) {
        const float* q_r0 = Q + qbase + (size_t)(q0 + mt * 16 + g) * DM;
        const float* q_r8 = Q + qbase + (size_t)(q0 + mt * 16 + g + 8) * DM;
        #pragma unroll
        for (int k8 = 0; k8 < 8; k8++) {
            const int cc = k8 * 8 + tig;
            qf[mt][k8][0] = f2tf32u(0.125f * __ldg(q_r0 + cc));
            qf[mt][k8][1] = f2tf32u(0.125f * __ldg(q_r8 + cc));
            qf[mt][k8][2] = f2tf32u(0.125f * __ldg(q_r0 + cc + 4));
            qf[mt][k8][3] = f2tf32u(0.125f * __ldg(q_r8 + cc + 4));
        }
    }

    const int pr = tid >> 1;            // row 0..63
    const int pc = (tid & 1) * 32;      // col base {0,32}
    auto kv_prefetch = [&](int kt, int buf) {
        const float* ksrc = K + kvbase + ((size_t)kt * 64 + pr) * DM + pc;
        const float* vsrc = V + kvbase + ((size_t)kt * 64 + pr) * DM + pc;
        float* kd = Ks + buf * 64 * 68 + pr * 68 + pc;
        float* vd = Vs + buf * 64 * 72 + pr * 72 + pc;
        #pragma unroll
        for (int j = 0; j < 8; j++) {
            cp16(kd + j * 4, ksrc + j * 4);
            cp16(vd + j * 4, vsrc + j * 4);
        }
        cp_commit();
    };

    kv_prefetch(0, 0);

    float o[2][8][4];
    #pragma unroll
    for (int mt = 0; mt < 2; mt++)
        #pragma unroll
        for (int nt = 0; nt < 8; nt++)
            #pragma unroll
            for (int j = 0; j < 4; j++) o[mt][nt][j] = 0.0f;
    float mrow0[2] = {-INFINITY, -INFINITY};
    float mrow1[2] = {-INFINITY, -INFINITY};
    float lrow0[2] = {0.0f, 0.0f};
    float lrow1[2] = {0.0f, 0.0f};

    const int NKT = SS / 64;
    for (int kt = 0; kt < NKT; kt++) {
        const int buf = kt & 1;
        __syncthreads();
        if (kt + 1 < NKT) {
            kv_prefetch(kt + 1, buf ^ 1);
            cp_wait<1>();
        } else {
            cp_wait<0>();
        }
        __syncthreads();

        const float* KsB = Ks + buf * 64 * 68;
        const float* VsB = Vs + buf * 64 * 72;

        // S = (Q*scale) K^T   (two m-tiles share every b-fragment)
        float s[2][8][4];
        #pragma unroll
        for (int mt = 0; mt < 2; mt++)
            #pragma unroll
            for (int nt = 0; nt < 8; nt++)
                #pragma unroll
                for (int j = 0; j < 4; j++) s[mt][nt][j] = 0.0f;

        #pragma unroll
        for (int k8 = 0; k8 < 8; k8++) {
            const int kk = k8 * 8;
            #pragma unroll
            for (int nt = 0; nt < 8; nt++) {
                unsigned b0 = __float_as_uint(KsB[(nt * 8 + g) * 68 + kk + tig]);
                unsigned b1 = __float_as_uint(KsB[(nt * 8 + g) * 68 + kk + tig + 4]);
                mma_tf32(s[0][nt], qf[0][k8][0], qf[0][k8][1], qf[0][k8][2], qf[0][k8][3], b0, b1);
                mma_tf32(s[1][nt], qf[1][k8][0], qf[1][k8][1], qf[1][k8][2], qf[1][k8][3], b0, b1);
            }
        }

        // online softmax per m-tile
        #pragma unroll
        for (int mt = 0; mt < 2; mt++) {
            float mx0 = -INFINITY, mx1 = -INFINITY;
            #pragma unroll
            for (int nt = 0; nt < 8; nt++) {
                mx0 = fmaxf(mx0, fmaxf(s[mt][nt][0], s[mt][nt][1]));
                mx1 = fmaxf(mx1, fmaxf(s[mt][nt][2], s[mt][nt][3]));
            }
            mx0 = fmaxf(mx0, __shfl_xor_sync(0xffffffffu, mx0, 1));
            mx0 = fmaxf(mx0, __shfl_xor_sync(0xffffffffu, mx0, 2));
            mx1 = fmaxf(mx1, __shfl_xor_sync(0xffffffffu, mx1, 1));
            mx1 = fmaxf(mx1, __shfl_xor_sync(0xffffffffu, mx1, 2));

            const float mn0 = fmaxf(mrow0[mt], mx0);
            const float mn1 = fmaxf(mrow1[mt], mx1);
            const float f0 = __expf(mrow0[mt] - mn0);
            const float f1 = __expf(mrow1[mt] - mn1);
            mrow0[mt] = mn0; mrow1[mt] = mn1;

            float sum0 = 0.0f, sum1 = 0.0f;
            const int r0 = (q0 + mt * 16 + g) * 68;
            const int r8 = (q0 + mt * 16 + g + 8) * 68;
            #pragma unroll
            for (int nt = 0; nt < 8; nt++) {
                float p0 = __expf(s[mt][nt][0] - mn0);
                float p1 = __expf(s[mt][nt][1] - mn0);
                float p2 = __expf(s[mt][nt][2] - mn1);
                float p3 = __expf(s[mt][nt][3] - mn1);
                sum0 += p0 + p1;
                sum1 += p2 + p3;
                const int kc = nt * 8 + 2 * tig;
                *(float2*)&Ps[r0 + kc] = make_float2(f2tf32f(p0), f2tf32f(p1));
                *(float2*)&Ps[r8 + kc] = make_float2(f2tf32f(p2), f2tf32f(p3));
            }
            sum0 += __shfl_xor_sync(0xffffffffu, sum0, 1);
            sum0 += __shfl_xor_sync(0xffffffffu, sum0, 2);
            sum1 += __shfl_xor_sync(0xffffffffu, sum1, 1);
            sum1 += __shfl_xor_sync(0xffffffffu, sum1, 2);
            lrow0[mt] = lrow0[mt] * f0 + sum0;
            lrow1[mt] = lrow1[mt] * f1 + sum1;

            #pragma unroll
            for (int nt = 0; nt < 8; nt++) {
                o[mt][nt][0] *= f0; o[mt][nt][1] *= f0;
                o[mt][nt][2] *= f1; o[mt][nt][3] *= f1;
            }
        }

        __syncwarp();   // Ps store -> Ps load (warp-private rows)

        // O += P V  (b-frags shared across the 2 m-tiles)
        #pragma unroll
        for (int k8 = 0; k8 < 8; k8++) {
            const int kk = k8 * 8;
            unsigned a[2][4];
            #pragma unroll
            for (int mt = 0; mt < 2; mt++) {
                const int r0 = (q0 + mt * 16 + g) * 68;
                const int r8 = (q0 + mt * 16 + g + 8) * 68;
                a[mt][0] = __float_as_uint(Ps[r0 + kk + tig]);
                a[mt][1] = __float_as_uint(Ps[r8 + kk + tig]);
                a[mt][2] = __float_as_uint(Ps[r0 + kk + tig + 4]);
                a[mt][3] = __float_as_uint(Ps[r8 + kk + tig + 4]);
            }
            #pragma unroll
            for (int nt = 0; nt < 8; nt++) {
                unsigned b0 = __float_as_uint(VsB[(kk + tig) * 72 + nt * 8 + g]);
                unsigned b1 = __float_as_uint(VsB[(kk + tig + 4) * 72 + nt * 8 + g]);
                mma_tf32(o[0][nt], a[0][0], a[0][1], a[0][2], a[0][3], b0, b1);
                mma_tf32(o[1][nt], a[1][0], a[1][1], a[1][2], a[1][3], b0, b1);
            }
        }
    }

    // normalize + write context
    #pragma unroll
    for (int mt = 0; mt < 2; mt++) {
        const float inv0 = 1.0f / lrow0[mt];
        const float inv1 = 1.0f / lrow1[mt];
        #pragma unroll
        for (int nt = 0; nt < 8; nt++) {
            const int c = nt * 8 + 2 * tig;
            *(float2*)&O[qbase + (size_t)(q0 + mt * 16 + g) * DM + c] =
                make_float2(o[mt][nt][0] * inv0, o[mt][nt][1] * inv0);
            *(float2*)&O[qbase + (size_t)(q0 + mt * 16 + g + 8) * DM + c] =
                make_float2(o[mt][nt][2] * inv1, o[mt][nt][3] * inv1);
        }
    }
}

// ---------------------------------------------------------------------------
extern "C" void kernel_launch(void* const* d_in, const int* in_sizes, int n_in,
                              void* d_out, int out_size) {
    const float* q  = (const float*)d_in[0];
    const float* k  = (const float*)d_in[1];
    const float* v  = (const float*)d_in[2];
    const float* Wq = (const float*)d_in[3];
    const float* Wk = (const float*)d_in[4];
    const float* Wv = (const float*)d_in[5];
    const float* Wo = (const float*)d_in[6];
    float* out = (float*)d_out;

    float *gQ, *gK, *gV, *gC;
    cudaGetSymbolAddress((void**)&gQ, g_Q);
    cudaGetSymbolAddress((void**)&gK, g_K);
    cudaGetSymbolAddress((void**)&gV, g_V);
    cudaGetSymbolAddress((void**)&gC, g_C);

    dim3 gGrid(DM / 128, MTOT / 128);

    // projections + fused RoPE on Q,K; K,V stored pre-rounded to tf32
    gemm_tf32_v2<true,  false><<<gGrid, 256>>>(q, Wq, gQ);
    gemm_tf32_v2<true,  true ><<<gGrid, 256>>>(k, Wk, gK);
    gemm_tf32_v2<false, true ><<<gGrid, 256>>>(v, Wv, gV);

    // flash attention
    const int smem = (2 * 64 * 68 + 2 * 64 * 72 + 128 * 68) * (int)sizeof(float);
    cudaFuncSetAttribute(flash_tf32_v4, cudaFuncAttributeMaxDynamicSharedMemorySize, smem);
    dim3 aGrid(SS / 128, NH, BB);
    flash_tf32_v4<<<aGrid, 128, smem>>>(gQ, gK, gV, gC);

    // output projection
    gemm_tf32_v2<false, false><<<gGrid, 256>>>(gC, Wo, out);
}

// round 6
// speedup vs baseline: 1.4670x; 1.3238x over previous
#include <cuda_runtime.h>
#include <cuda_fp16.h>
#include <math.h>

#define BB 4
#define SS 2048
#define DM 1024
#define NH 16
#define DK 64
#define MTOT (BB*SS)

// scratch (device globals; allocation-free at launch time)
__device__ __half g_Qh[(size_t)MTOT*DM];
__device__ __half g_Kh[(size_t)MTOT*DM];
__device__ __half g_Vh[(size_t)MTOT*DM];
__device__ float  g_C [(size_t)MTOT*DM];

// ---------------------------------------------------------------------------
// helpers
// ---------------------------------------------------------------------------
__device__ __forceinline__ unsigned f2tf32u(float x) {
    unsigned y;
    asm("cvt.rna.tf32.f32 %0, %1;" : "=r"(y) : "f"(x));
    return y;
}

__device__ __forceinline__ void mma_tf32(float c[4],
                                         unsigned a0, unsigned a1, unsigned a2, unsigned a3,
                                         unsigned b0, unsigned b1) {
    asm volatile(
        "mma.sync.aligned.m16n8k8.row.col.f32.tf32.tf32.f32 "
        "{%0,%1,%2,%3},{%4,%5,%6,%7},{%8,%9},{%0,%1,%2,%3};"
        : "+f"(c[0]), "+f"(c[1]), "+f"(c[2]), "+f"(c[3])
        : "r"(a0), "r"(a1), "r"(a2), "r"(a3), "r"(b0), "r"(b1));
}

__device__ __forceinline__ void mma_f16(float c[4],
                                        unsigned a0, unsigned a1, unsigned a2, unsigned a3,
                                        unsigned b0, unsigned b1) {
    asm volatile(
        "mma.sync.aligned.m16n8k16.row.col.f32.f16.f16.f32 "
        "{%0,%1,%2,%3},{%4,%5,%6,%7},{%8,%9},{%0,%1,%2,%3};"
        : "+f"(c[0]), "+f"(c[1]), "+f"(c[2]), "+f"(c[3])
        : "r"(a0), "r"(a1), "r"(a2), "r"(a3), "r"(b0), "r"(b1));
}

__device__ __forceinline__ unsigned packh2(float a, float b) {
    __half2 h = __floats2half2_rn(a, b);
    return *(unsigned*)&h;
}

__device__ __forceinline__ void cp16(void* dst_smem, const void* src_gmem) {
    unsigned s = (unsigned)__cvta_generic_to_shared(dst_smem);
    asm volatile("cp.async.cg.shared.global [%0], [%1], 16;" :: "r"(s), "l"(src_gmem));
}
__device__ __forceinline__ void cp_commit() { asm volatile("cp.async.commit_group;"); }
template<int N> __device__ __forceinline__ void cp_wait() {
    asm volatile("cp.async.wait_group %0;" :: "n"(N));
}

// log2(10000)/32
#define ROPE_L2 0.41524101186f

// ---------------------------------------------------------------------------
// TF32 GEMM (v2 shape — measured good): BM=BN=128, BK=16, 256 thr = 8 warps
// (4x2), warp tile 32x64. cp.async double-buffered.
// MODE: 0 = fp32 store; 1 = rope + 0.125 scale + half store (Q);
//       2 = rope + half store (K); 3 = half store (V).
// ---------------------------------------------------------------------------
template<int MODE>
__global__ __launch_bounds__(256) void gemm_tf32_v2(const float* __restrict__ A,
                                                    const float* __restrict__ W,
                                                    void* __restrict__ Cout) {
    __shared__ float As[2][128][20];
    __shared__ float Bs[2][16][136];

    const int tid  = threadIdx.x;
    const int wid  = tid >> 5;
    const int lane = tid & 31;
    const int g    = lane >> 2;
    const int tig  = lane & 3;
    const int rw   = wid >> 1;
    const int cw   = wid & 1;
    const int m0   = blockIdx.y * 128;
    const int n0   = blockIdx.x * 128;

    const int lr = tid >> 1;
    const int lc = (tid & 1) * 8;
    const int wr = tid >> 4;
    const int wc = (tid & 15) * 8;

    float acc[2][8][4];
    #pragma unroll
    for (int i = 0; i < 2; i++)
        #pragma unroll
        for (int j = 0; j < 8; j++)
            #pragma unroll
            for (int l = 0; l < 4; l++) acc[i][j][l] = 0.0f;

    const float* asrc = A + (size_t)(m0 + lr) * DM + lc;
    const float* bsrc = W + (size_t)wr * DM + n0 + wc;

    cp16(&As[0][lr][lc],     asrc);
    cp16(&As[0][lr][lc + 4], asrc + 4);
    cp16(&Bs[0][wr][wc],     bsrc);
    cp16(&Bs[0][wr][wc + 4], bsrc + 4);
    cp_commit();

    const int NT = DM / 16;
    for (int t = 0; t < NT; t++) {
        const int buf = t & 1;
        if (t + 1 < NT) {
            const float* a2 = asrc + (t + 1) * 16;
            const float* b2 = bsrc + (size_t)(t + 1) * 16 * DM;
            cp16(&As[buf ^ 1][lr][lc],     a2);
            cp16(&As[buf ^ 1][lr][lc + 4], a2 + 4);
            cp16(&Bs[buf ^ 1][wr][wc],     b2);
            cp16(&Bs[buf ^ 1][wr][wc + 4], b2 + 4);
            cp_commit();
            cp_wait<1>();
        } else {
            cp_wait<0>();
        }
        __syncthreads();

        #pragma unroll
        for (int ks = 0; ks < 16; ks += 8) {
            unsigned a[2][4];
            #pragma unroll
            for (int mt = 0; mt < 2; mt++) {
                const int r = rw * 32 + mt * 16;
                a[mt][0] = f2tf32u(As[buf][r + g][ks + tig]);
                a[mt][1] = f2tf32u(As[buf][r + g + 8][ks + tig]);
                a[mt][2] = f2tf32u(As[buf][r + g][ks + tig + 4]);
                a[mt][3] = f2tf32u(As[buf][r + g + 8][ks + tig + 4]);
            }
            unsigned b[8][2];
            #pragma unroll
            for (int nt = 0; nt < 8; nt++) {
                const int n = cw * 64 + nt * 8;
                b[nt][0] = f2tf32u(Bs[buf][ks + tig][n + g]);
                b[nt][1] = f2tf32u(Bs[buf][ks + tig + 4][n + g]);
            }
            #pragma unroll
            for (int mt = 0; mt < 2; mt++)
                #pragma unroll
                for (int nt = 0; nt < 8; nt++)
                    mma_tf32(acc[mt][nt], a[mt][0], a[mt][1], a[mt][2], a[mt][3],
                             b[nt][0], b[nt][1]);
        }
        __syncthreads();
    }

    #pragma unroll
    for (int mt = 0; mt < 2; mt++) {
        const int r = m0 + rw * 32 + mt * 16 + g;
        const int pos0 = r & (SS - 1);
        const int pos8 = (r + 8) & (SS - 1);
        #pragma unroll
        for (int nt = 0; nt < 8; nt++) {
            const int c = n0 + cw * 64 + nt * 8 + 2 * tig;
            float y0 = acc[mt][nt][0], y1 = acc[mt][nt][1];
            float y2 = acc[mt][nt][2], y3 = acc[mt][nt][3];
            if (MODE == 1 || MODE == 2) {
                const int i = (c & 63) >> 1;
                const float inv = exp2f(-(float)i * ROPE_L2);
                float s0, c0, s8, c8;
                sincosf((float)pos0 * inv, &s0, &c0);
                sincosf((float)pos8 * inv, &s8, &c8);
                float x1 = y0, x2 = y1;
                y0 = x1 * c0 - x2 * s0;
                y1 = x1 * s0 + x2 * c0;
                x1 = y2; x2 = y3;
                y2 = x1 * c8 - x2 * s8;
                y3 = x1 * s8 + x2 * c8;
            }
            if (MODE == 1) { y0 *= 0.125f; y1 *= 0.125f; y2 *= 0.125f; y3 *= 0.125f; }
            if (MODE == 0) {
                float* C = (float*)Cout;
                *(float2*)&C[(size_t)r * DM + c]       = make_float2(y0, y1);
                *(float2*)&C[(size_t)(r + 8) * DM + c] = make_float2(y2, y3);
            } else {
                __half* C = (__half*)Cout;
                *(__half2*)&C[(size_t)r * DM + c]       = __floats2half2_rn(y0, y1);
                *(__half2*)&C[(size_t)(r + 8) * DM + c] = __floats2half2_rn(y2, y3);
            }
        }
    }
}

// ---------------------------------------------------------------------------
// Flash attention v5, fp16 MMA (m16n8k16), fp32 accum & softmax.
// BM=128 q rows, BN=64 keys/iter, DK=64. 256 threads = 8 warps x 16 q rows.
// Q pre-scaled (1/8) fp16 in gmem -> A-frags in regs. P stays in registers
// (C-frag of S == A-frag of PV). K/V fp16 smem, double-buffered cp.async.
// ---------------------------------------------------------------------------
__global__ __launch_bounds__(256, 2) void flash_f16(const __half* __restrict__ Qh,
                                                    const __half* __restrict__ Kh,
                                                    const __half* __restrict__ Vh,
                                                    float* __restrict__ O) {
    __shared__ __half Ks[2][64][72];   // [key][d], pad 72 halves (144B rows)
    __shared__ __half Vs[2][64][72];   // [key][d]

    const int tid  = threadIdx.x;
    const int wid  = tid >> 5;
    const int lane = tid & 31;
    const int g    = lane >> 2;
    const int tig  = lane & 3;
    const int h    = blockIdx.y;
    const int b    = blockIdx.z;
    const int q0   = wid * 16;
    const size_t qbase = ((size_t)b * SS + blockIdx.x * 128) * DM + h * DK;
    const size_t kvbase = (size_t)b * SS * DM + h * DK;

    // Q A-fragments (fp16, pre-scaled): 4 k16-blocks x 4 regs
    unsigned qf[4][4];
    {
        const __half* q_r0 = Qh + qbase + (size_t)(q0 + g) * DM;
        const __half* q_r8 = Qh + qbase + (size_t)(q0 + g + 8) * DM;
        #pragma unroll
        for (int kb = 0; kb < 4; kb++) {
            const int cc = kb * 16 + 2 * tig;
            qf[kb][0] = *(const unsigned*)(q_r0 + cc);
            qf[kb][1] = *(const unsigned*)(q_r8 + cc);
            qf[kb][2] = *(const unsigned*)(q_r0 + cc + 8);
            qf[kb][3] = *(const unsigned*)(q_r8 + cc + 8);
        }
    }

    const int pr = tid >> 2;            // key row 0..63
    const int pc = (tid & 3) * 16;      // col base in halves {0,16,32,48}
    auto kv_prefetch = [&](int kt, int buf) {
        const __half* ksrc = Kh + kvbase + ((size_t)kt * 64 + pr) * DM + pc;
        const __half* vsrc = Vh + kvbase + ((size_t)kt * 64 + pr) * DM + pc;
        cp16(&Ks[buf][pr][pc],     ksrc);
        cp16(&Ks[buf][pr][pc + 8], ksrc + 8);
        cp16(&Vs[buf][pr][pc],     vsrc);
        cp16(&Vs[buf][pr][pc + 8], vsrc + 8);
        cp_commit();
    };

    kv_prefetch(0, 0);

    float o[8][4];
    #pragma unroll
    for (int nt = 0; nt < 8; nt++)
        #pragma unroll
        for (int j = 0; j < 4; j++) o[nt][j] = 0.0f;
    float mrow0 = -INFINITY, mrow1 = -INFINITY;
    float lrow0 = 0.0f, lrow1 = 0.0f;

    const int NKT = SS / 64;
    for (int kt = 0; kt < NKT; kt++) {
        const int buf = kt & 1;
        __syncthreads();
        if (kt + 1 < NKT) {
            kv_prefetch(kt + 1, buf ^ 1);
            cp_wait<1>();
        } else {
            cp_wait<0>();
        }
        __syncthreads();

        // S = (Q/8) K^T  -- fp16 k16 MMAs; K b-frags are contiguous half2
        float s[8][4];
        #pragma unroll
        for (int nt = 0; nt < 8; nt++)
            #pragma unroll
            for (int j = 0; j < 4; j++) s[nt][j] = 0.0f;

        #pragma unroll
        for (int kb = 0; kb < 4; kb++) {
            const int cc = kb * 16 + 2 * tig;
            #pragma unroll
            for (int nt = 0; nt < 8; nt++) {
                const int n = nt * 8 + g;
                unsigned b0 = *(const unsigned*)&Ks[buf][n][cc];
                unsigned b1 = *(const unsigned*)&Ks[buf][n][cc + 8];
                mma_f16(s[nt], qf[kb][0], qf[kb][1], qf[kb][2], qf[kb][3], b0, b1);
            }
        }

        // online softmax (rows q0+g, q0+g+8); P packed to fp16 in registers
        float mx0 = -INFINITY, mx1 = -INFINITY;
        #pragma unroll
        for (int nt = 0; nt < 8; nt++) {
            mx0 = fmaxf(mx0, fmaxf(s[nt][0], s[nt][1]));
            mx1 = fmaxf(mx1, fmaxf(s[nt][2], s[nt][3]));
        }
        mx0 = fmaxf(mx0, __shfl_xor_sync(0xffffffffu, mx0, 1));
        mx0 = fmaxf(mx0, __shfl_xor_sync(0xffffffffu, mx0, 2));
        mx1 = fmaxf(mx1, __shfl_xor_sync(0xffffffffu, mx1, 1));
        mx1 = fmaxf(mx1, __shfl_xor_sync(0xffffffffu, mx1, 2));

        const float mn0 = fmaxf(mrow0, mx0);
        const float mn1 = fmaxf(mrow1, mx1);
        const float f0 = __expf(mrow0 - mn0);
        const float f1 = __expf(mrow1 - mn1);
        mrow0 = mn0; mrow1 = mn1;

        unsigned ph[8][2];
        float sum0 = 0.0f, sum1 = 0.0f;
        #pragma unroll
        for (int nt = 0; nt < 8; nt++) {
            float p0 = __expf(s[nt][0] - mn0);
            float p1 = __expf(s[nt][1] - mn0);
            float p2 = __expf(s[nt][2] - mn1);
            float p3 = __expf(s[nt][3] - mn1);
            sum0 += p0 + p1;
            sum1 += p2 + p3;
            ph[nt][0] = packh2(p0, p1);   // row g,   cols nt*8+2tig,+1
            ph[nt][1] = packh2(p2, p3);   // row g+8
        }
        sum0 += __shfl_xor_sync(0xffffffffu, sum0, 1);
        sum0 += __shfl_xor_sync(0xffffffffu, sum0, 2);
        sum1 += __shfl_xor_sync(0xffffffffu, sum1, 1);
        sum1 += __shfl_xor_sync(0xffffffffu, sum1, 2);
        lrow0 = lrow0 * f0 + sum0;
        lrow1 = lrow1 * f1 + sum1;

        #pragma unroll
        for (int nt = 0; nt < 8; nt++) {
            o[nt][0] *= f0; o[nt][1] *= f0;
            o[nt][2] *= f1; o[nt][3] *= f1;
        }

        // O += P V  -- P A-frags already in registers (ph)
        #pragma unroll
        for (int kb = 0; kb < 4; kb++) {
            const unsigned a0 = ph[2 * kb][0];
            const unsigned a1 = ph[2 * kb][1];
            const unsigned a2 = ph[2 * kb + 1][0];
            const unsigned a3 = ph[2 * kb + 1][1];
            const int k0i = kb * 16 + 2 * tig;
            #pragma unroll
            for (int nt = 0; nt < 8; nt++) {
                const int n = nt * 8 + g;
                __half2 v0 = __halves2half2(Vs[buf][k0i][n],     Vs[buf][k0i + 1][n]);
                __half2 v1 = __halves2half2(Vs[buf][k0i + 8][n], Vs[buf][k0i + 9][n]);
                mma_f16(o[nt], a0, a1, a2, a3, *(unsigned*)&v0, *(unsigned*)&v1);
            }
        }
    }

    // normalize + write context (fp32 for the Wo GEMM)
    const float inv0 = 1.0f / lrow0;
    const float inv1 = 1.0f / lrow1;
    #pragma unroll
    for (int nt = 0; nt < 8; nt++) {
        const int c = nt * 8 + 2 * tig;
        *(float2*)&O[qbase + (size_t)(q0 + g) * DM + c] =
            make_float2(o[nt][0] * inv0, o[nt][1] * inv0);
        *(float2*)&O[qbase + (size_t)(q0 + g + 8) * DM + c] =
            make_float2(o[nt][2] * inv1, o[nt][3] * inv1);
    }
}

// ---------------------------------------------------------------------------
extern "C" void kernel_launch(void* const* d_in, const int* in_sizes, int n_in,
                              void* d_out, int out_size) {
    const float* q  = (const float*)d_in[0];
    const float* k  = (const float*)d_in[1];
    const float* v  = (const float*)d_in[2];
    const float* Wq = (const float*)d_in[3];
    const float* Wk = (const float*)d_in[4];
    const float* Wv = (const float*)d_in[5];
    const float* Wo = (const float*)d_in[6];
    float* out = (float*)d_out;

    __half *gQh, *gKh, *gVh;
    float *gC;
    cudaGetSymbolAddress((void**)&gQh, g_Qh);
    cudaGetSymbolAddress((void**)&gKh, g_Kh);
    cudaGetSymbolAddress((void**)&gVh, g_Vh);
    cudaGetSymbolAddress((void**)&gC,  g_C);

    dim3 gGrid(DM / 128, MTOT / 128);

    // projections: Q (rope+scale->half), K (rope->half), V (->half)
    gemm_tf32_v2<1><<<gGrid, 256>>>(q, Wq, gQh);
    gemm_tf32_v2<2><<<gGrid, 256>>>(k, Wk, gKh);
    gemm_tf32_v2<3><<<gGrid, 256>>>(v, Wv, gVh);

    // flash attention (fp16 tensor cores, fp32 softmax)
    dim3 aGrid(SS / 128, NH, BB);
    flash_f16<<<aGrid, 256>>>(gQh, gKh, gVh, gC);

    // output projection (tf32)
    gemm_tf32_v2<0><<<gGrid, 256>>>(gC, Wo, out);
}

// round 7
// speedup vs baseline: 2.0653x; 1.4078x over previous
#include <cuda_runtime.h>
#include <cuda_fp16.h>
#include <math.h>

#define BB 4
#define SS 2048
#define DM 1024
#define NH 16
#define DK 64
#define MTOT (BB*SS)

// scratch (device globals; allocation-free at launch time)
__device__ __half g_qi[(size_t)MTOT*DM];   // converted inputs
__device__ __half g_ki[(size_t)MTOT*DM];
__device__ __half g_vi[(size_t)MTOT*DM];
__device__ __half g_Wqt[(size_t)DM*DM];    // transposed fp16 weights [N][K]
__device__ __half g_Wkt[(size_t)DM*DM];
__device__ __half g_Wvt[(size_t)DM*DM];
__device__ __half g_Wot[(size_t)DM*DM];
__device__ __half g_Qh[(size_t)MTOT*DM];   // projected Q (rope, /8)
__device__ __half g_Kh[(size_t)MTOT*DM];   // projected K (rope)
__device__ __half g_Vh[(size_t)MTOT*DM];   // projected V
__device__ __half g_Ch[(size_t)MTOT*DM];   // attention context

// ---------------------------------------------------------------------------
// helpers
// ---------------------------------------------------------------------------
__device__ __forceinline__ void mma_f16(float c[4],
                                        unsigned a0, unsigned a1, unsigned a2, unsigned a3,
                                        unsigned b0, unsigned b1) {
    asm volatile(
        "mma.sync.aligned.m16n8k16.row.col.f32.f16.f16.f32 "
        "{%0,%1,%2,%3},{%4,%5,%6,%7},{%8,%9},{%0,%1,%2,%3};"
        : "+f"(c[0]), "+f"(c[1]), "+f"(c[2]), "+f"(c[3])
        : "r"(a0), "r"(a1), "r"(a2), "r"(a3), "r"(b0), "r"(b1));
}

__device__ __forceinline__ unsigned packh2(float a, float b) {
    __half2 h = __floats2half2_rn(a, b);
    return *(unsigned*)&h;
}

__device__ __forceinline__ void cp16(void* dst_smem, const void* src_gmem) {
    unsigned s = (unsigned)__cvta_generic_to_shared(dst_smem);
    asm volatile("cp.async.cg.shared.global [%0], [%1], 16;" :: "r"(s), "l"(src_gmem));
}
__device__ __forceinline__ void cp_commit() { asm volatile("cp.async.commit_group;"); }
template<int N> __device__ __forceinline__ void cp_wait() {
    asm volatile("cp.async.wait_group %0;" :: "n"(N));
}

// log2(10000)/32
#define ROPE_L2 0.41524101186f

// ---------------------------------------------------------------------------
// converts
// ---------------------------------------------------------------------------
__global__ void cvt_f2h(const float* __restrict__ X, __half* __restrict__ Y, int n8) {
    int i = blockIdx.x * blockDim.x + threadIdx.x;
    if (i >= n8) return;
    const float4 v0 = *(const float4*)(X + (size_t)i * 8);
    const float4 v1 = *(const float4*)(X + (size_t)i * 8 + 4);
    __half2 h[4] = {__floats2half2_rn(v0.x, v0.y), __floats2half2_rn(v0.z, v0.w),
                    __floats2half2_rn(v1.x, v1.y), __floats2half2_rn(v1.z, v1.w)};
    *(uint4*)(Y + (size_t)i * 8) = *(uint4*)h;
}

// W [K][N] fp32 -> Wt [N][K] fp16
__global__ void cvt_wT(const float* __restrict__ W, __half* __restrict__ Wt) {
    __shared__ float t[32][33];
    const int bn = blockIdx.x * 32, bk = blockIdx.y * 32;
    const int x = threadIdx.x, y = threadIdx.y;   // x:0..31, y:0..7
    #pragma unroll
    for (int i = 0; i < 32; i += 8)
        t[y + i][x] = W[(size_t)(bk + y + i) * DM + bn + x];   // t[k][n]
    __syncthreads();
    #pragma unroll
    for (int i = 0; i < 32; i += 8)
        Wt[(size_t)(bn + y + i) * DM + bk + x] = __float2half(t[x][y + i]);
}

// ---------------------------------------------------------------------------
// FP16 GEMM: C[M,N] = A[M,K] * Bt[N,K]^T. BM=BN=128, BK=32, 256 thr = 8 warps
// (4x2), warp tile 32x64 via m16n8k16. cp.async double-buffered.
// MODE: 0 = fp32 store; 1 = rope + 0.125 scale + half; 2 = rope + half; 3 = half.
// ---------------------------------------------------------------------------
template<int MODE>
__global__ __launch_bounds__(256) void gemm_f16(const __half* __restrict__ A,
                                                const __half* __restrict__ Bt,
                                                void* __restrict__ Cout) {
    __shared__ __half As[2][128][40];   // [m][k] pad 40 halves -> conflict-free
    __shared__ __half Bs[2][128][40];   // [n][k] pad 40

    const int tid  = threadIdx.x;
    const int wid  = tid >> 5;
    const int lane = tid & 31;
    const int g    = lane >> 2;
    const int tig  = lane & 3;
    const int rw   = wid >> 1;
    const int cw   = wid & 1;
    const int m0   = blockIdx.y * 128;
    const int n0   = blockIdx.x * 128;

    const int lr = tid >> 1;            // row 0..127
    const int lc = (tid & 1) * 16;      // col base in halves {0,16}

    float acc[2][8][4];
    #pragma unroll
    for (int i = 0; i < 2; i++)
        #pragma unroll
        for (int j = 0; j < 8; j++)
            #pragma unroll
            for (int l = 0; l < 4; l++) acc[i][j][l] = 0.0f;

    const __half* asrc = A  + (size_t)(m0 + lr) * DM + lc;
    const __half* bsrc = Bt + (size_t)(n0 + lr) * DM + lc;

    cp16(&As[0][lr][lc],     asrc);
    cp16(&As[0][lr][lc + 8], asrc + 8);
    cp16(&Bs[0][lr][lc],     bsrc);
    cp16(&Bs[0][lr][lc + 8], bsrc + 8);
    cp_commit();

    const int NT = DM / 32;
    for (int t = 0; t < NT; t++) {
        const int buf = t & 1;
        if (t + 1 < NT) {
            const __half* a2 = asrc + (t + 1) * 32;
            const __half* b2 = bsrc + (t + 1) * 32;
            cp16(&As[buf ^ 1][lr][lc],     a2);
            cp16(&As[buf ^ 1][lr][lc + 8], a2 + 8);
            cp16(&Bs[buf ^ 1][lr][lc],     b2);
            cp16(&Bs[buf ^ 1][lr][lc + 8], b2 + 8);
            cp_commit();
            cp_wait<1>();
        } else {
            cp_wait<0>();
        }
        __syncthreads();

        #pragma unroll
        for (int kb = 0; kb < 2; kb++) {
            const int kk = kb * 16 + 2 * tig;
            unsigned a[2][4];
            #pragma unroll
            for (int mt = 0; mt < 2; mt++) {
                const int r = rw * 32 + mt * 16;
                a[mt][0] = *(const unsigned*)&As[buf][r + g][kk];
                a[mt][1] = *(const unsigned*)&As[buf][r + g + 8][kk];
                a[mt][2] = *(const unsigned*)&As[buf][r + g][kk + 8];
                a[mt][3] = *(const unsigned*)&As[buf][r + g + 8][kk + 8];
            }
            unsigned b[8][2];
            #pragma unroll
            for (int nt = 0; nt < 8; nt++) {
                const int n = cw * 64 + nt * 8 + g;
                b[nt][0] = *(const unsigned*)&Bs[buf][n][kk];
                b[nt][1] = *(const unsigned*)&Bs[buf][n][kk + 8];
            }
            #pragma unroll
            for (int mt = 0; mt < 2; mt++)
                #pragma unroll
                for (int nt = 0; nt < 8; nt++)
                    mma_f16(acc[mt][nt], a[mt][0], a[mt][1], a[mt][2], a[mt][3],
                            b[nt][0], b[nt][1]);
        }
        __syncthreads();
    }

    #pragma unroll
    for (int mt = 0; mt < 2; mt++) {
        const int r = m0 + rw * 32 + mt * 16 + g;
        const int pos0 = r & (SS - 1);
        const int pos8 = (r + 8) & (SS - 1);
        #pragma unroll
        for (int nt = 0; nt < 8; nt++) {
            const int c = n0 + cw * 64 + nt * 8 + 2 * tig;
            float y0 = acc[mt][nt][0], y1 = acc[mt][nt][1];
            float y2 = acc[mt][nt][2], y3 = acc[mt][nt][3];
            if (MODE == 1 || MODE == 2) {
                const int i = (c & 63) >> 1;
                const float inv = exp2f(-(float)i * ROPE_L2);
                float s0, c0, s8, c8;
                sincosf((float)pos0 * inv, &s0, &c0);
                sincosf((float)pos8 * inv, &s8, &c8);
                float x1 = y0, x2 = y1;
                y0 = x1 * c0 - x2 * s0;
                y1 = x1 * s0 + x2 * c0;
                x1 = y2; x2 = y3;
                y2 = x1 * c8 - x2 * s8;
                y3 = x1 * s8 + x2 * c8;
            }
            if (MODE == 1) { y0 *= 0.125f; y1 *= 0.125f; y2 *= 0.125f; y3 *= 0.125f; }
            if (MODE == 0) {
                float* C = (float*)Cout;
                *(float2*)&C[(size_t)r * DM + c]       = make_float2(y0, y1);
                *(float2*)&C[(size_t)(r + 8) * DM + c] = make_float2(y2, y3);
            } else {
                __half* C = (__half*)Cout;
                *(__half2*)&C[(size_t)r * DM + c]       = __floats2half2_rn(y0, y1);
                *(__half2*)&C[(size_t)(r + 8) * DM + c] = __floats2half2_rn(y2, y3);
            }
        }
    }
}

// ---------------------------------------------------------------------------
// Flash attention, fp16 MMA (m16n8k16), fp32 accum & softmax.
// BM=128 q rows, BN=64 keys/iter, DK=64. 256 threads = 8 warps x 16 q rows.
// Q pre-scaled (1/8) fp16 -> A-frags in regs. P stays in registers.
// Writes context as fp16 for the fp16 Wo GEMM.
// ---------------------------------------------------------------------------
__global__ __launch_bounds__(256, 2) void flash_f16(const __half* __restrict__ Qh,
                                                    const __half* __restrict__ Kh,
                                                    const __half* __restrict__ Vh,
                                                    __half* __restrict__ O) {
    __shared__ __half Ks[2][64][72];
    __shared__ __half Vs[2][64][72];

    const int tid  = threadIdx.x;
    const int wid  = tid >> 5;
    const int lane = tid & 31;
    const int g    = lane >> 2;
    const int tig  = lane & 3;
    const int h    = blockIdx.y;
    const int b    = blockIdx.z;
    const int q0   = wid * 16;
    const size_t qbase = ((size_t)b * SS + blockIdx.x * 128) * DM + h * DK;
    const size_t kvbase = (size_t)b * SS * DM + h * DK;

    unsigned qf[4][4];
    {
        const __half* q_r0 = Qh + qbase + (size_t)(q0 + g) * DM;
        const __half* q_r8 = Qh + qbase + (size_t)(q0 + g + 8) * DM;
        #pragma unroll
        for (int kb = 0; kb < 4; kb++) {
            const int cc = kb * 16 + 2 * tig;
            qf[kb][0] = *(const unsigned*)(q_r0 + cc);
            qf[kb][1] = *(const unsigned*)(q_r8 + cc);
            qf[kb][2] = *(const unsigned*)(q_r0 + cc + 8);
            qf[kb][3] = *(const unsigned*)(q_r8 + cc + 8);
        }
    }

    const int pr = tid >> 2;
    const int pc = (tid & 3) * 16;
    auto kv_prefetch = [&](int kt, int buf) {
        const __half* ksrc = Kh + kvbase + ((size_t)kt * 64 + pr) * DM + pc;
        const __half* vsrc = Vh + kvbase + ((size_t)kt * 64 + pr) * DM + pc;
        cp16(&Ks[buf][pr][pc],     ksrc);
        cp16(&Ks[buf][pr][pc + 8], ksrc + 8);
        cp16(&Vs[buf][pr][pc],     vsrc);
        cp16(&Vs[buf][pr][pc + 8], vsrc + 8);
        cp_commit();
    };

    kv_prefetch(0, 0);

    float o[8][4];
    #pragma unroll
    for (int nt = 0; nt < 8; nt++)
        #pragma unroll
        for (int j = 0; j < 4; j++) o[nt][j] = 0.0f;
    float mrow0 = -INFINITY, mrow1 = -INFINITY;
    float lrow0 = 0.0f, lrow1 = 0.0f;

    const int NKT = SS / 64;
    for (int kt = 0; kt < NKT; kt++) {
        const int buf = kt & 1;
        __syncthreads();
        if (kt + 1 < NKT) {
            kv_prefetch(kt + 1, buf ^ 1);
            cp_wait<1>();
        } else {
            cp_wait<0>();
        }
        __syncthreads();

        float s[8][4];
        #pragma unroll
        for (int nt = 0; nt < 8; nt++)
            #pragma unroll
            for (int j = 0; j < 4; j++) s[nt][j] = 0.0f;

        #pragma unroll
        for (int kb = 0; kb < 4; kb++) {
            const int cc = kb * 16 + 2 * tig;
            #pragma unroll
            for (int nt = 0; nt < 8; nt++) {
                const int n = nt * 8 + g;
                unsigned b0 = *(const unsigned*)&Ks[buf][n][cc];
                unsigned b1 = *(const unsigned*)&Ks[buf][n][cc + 8];
                mma_f16(s[nt], qf[kb][0], qf[kb][1], qf[kb][2], qf[kb][3], b0, b1);
            }
        }

        float mx0 = -INFINITY, mx1 = -INFINITY;
        #pragma unroll
        for (int nt = 0; nt < 8; nt++) {
            mx0 = fmaxf(mx0, fmaxf(s[nt][0], s[nt][1]));
            mx1 = fmaxf(mx1, fmaxf(s[nt][2], s[nt][3]));
        }
        mx0 = fmaxf(mx0, __shfl_xor_sync(0xffffffffu, mx0, 1));
        mx0 = fmaxf(mx0, __shfl_xor_sync(0xffffffffu, mx0, 2));
        mx1 = fmaxf(mx1, __shfl_xor_sync(0xffffffffu, mx1, 1));
        mx1 = fmaxf(mx1, __shfl_xor_sync(0xffffffffu, mx1, 2));

        const float mn0 = fmaxf(mrow0, mx0);
        const float mn1 = fmaxf(mrow1, mx1);
        const float f0 = __expf(mrow0 - mn0);
        const float f1 = __expf(mrow1 - mn1);
        mrow0 = mn0; mrow1 = mn1;

        unsigned ph[8][2];
        float sum0 = 0.0f, sum1 = 0.0f;
        #pragma unroll
        for (int nt = 0; nt < 8; nt++) {
            float p0 = __expf(s[nt][0] - mn0);
            float p1 = __expf(s[nt][1] - mn0);
            float p2 = __expf(s[nt][2] - mn1);
            float p3 = __expf(s[nt][3] - mn1);
            sum0 += p0 + p1;
            sum1 += p2 + p3;
            ph[nt][0] = packh2(p0, p1);
            ph[nt][1] = packh2(p2, p3);
        }
        sum0 += __shfl_xor_sync(0xffffffffu, sum0, 1);
        sum0 += __shfl_xor_sync(0xffffffffu, sum0, 2);
        sum1 += __shfl_xor_sync(0xffffffffu, sum1, 1);
        sum1 += __shfl_xor_sync(0xffffffffu, sum1, 2);
        lrow0 = lrow0 * f0 + sum0;
        lrow1 = lrow1 * f1 + sum1;

        #pragma unroll
        for (int nt = 0; nt < 8; nt++) {
            o[nt][0] *= f0; o[nt][1] *= f0;
            o[nt][2] *= f1; o[nt][3] *= f1;
        }

        #pragma unroll
        for (int kb = 0; kb < 4; kb++) {
            const unsigned a0 = ph[2 * kb][0];
            const unsigned a1 = ph[2 * kb][1];
            const unsigned a2 = ph[2 * kb + 1][0];
            const unsigned a3 = ph[2 * kb + 1][1];
            const int k0i = kb * 16 + 2 * tig;
            #pragma unroll
            for (int nt = 0; nt < 8; nt++) {
                const int n = nt * 8 + g;
                __half2 v0 = __halves2half2(Vs[buf][k0i][n],     Vs[buf][k0i + 1][n]);
                __half2 v1 = __halves2half2(Vs[buf][k0i + 8][n], Vs[buf][k0i + 9][n]);
                mma_f16(o[nt], a0, a1, a2, a3, *(unsigned*)&v0, *(unsigned*)&v1);
            }
        }
    }

    const float inv0 = 1.0f / lrow0;
    const float inv1 = 1.0f / lrow1;
    #pragma unroll
    for (int nt = 0; nt < 8; nt++) {
        const int c = nt * 8 + 2 * tig;
        *(__half2*)&O[qbase + (size_t)(q0 + g) * DM + c] =
            __floats2half2_rn(o[nt][0] * inv0, o[nt][1] * inv0);
        *(__half2*)&O[qbase + (size_t)(q0 + g + 8) * DM + c] =
            __floats2half2_rn(o[nt][2] * inv1, o[nt][3] * inv1);
    }
}

// ---------------------------------------------------------------------------
extern "C" void kernel_launch(void* const* d_in, const int* in_sizes, int n_in,
                              void* d_out, int out_size) {
    const float* q  = (const float*)d_in[0];
    const float* k  = (const float*)d_in[1];
    const float* v  = (const float*)d_in[2];
    const float* Wq = (const float*)d_in[3];
    const float* Wk = (const float*)d_in[4];
    const float* Wv = (const float*)d_in[5];
    const float* Wo = (const float*)d_in[6];
    float* out = (float*)d_out;

    __half *qi, *ki, *vi, *Wqt, *Wkt, *Wvt, *Wot, *Qh, *Kh, *Vh, *Ch;
    cudaGetSymbolAddress((void**)&qi,  g_qi);
    cudaGetSymbolAddress((void**)&ki,  g_ki);
    cudaGetSymbolAddress((void**)&vi,  g_vi);
    cudaGetSymbolAddress((void**)&Wqt, g_Wqt);
    cudaGetSymbolAddress((void**)&Wkt, g_Wkt);
    cudaGetSymbolAddress((void**)&Wvt, g_Wvt);
    cudaGetSymbolAddress((void**)&Wot, g_Wot);
    cudaGetSymbolAddress((void**)&Qh,  g_Qh);
    cudaGetSymbolAddress((void**)&Kh,  g_Kh);
    cudaGetSymbolAddress((void**)&Vh,  g_Vh);
    cudaGetSymbolAddress((void**)&Ch,  g_Ch);

    // converts
    const int n8 = MTOT * DM / 8;
    cvt_f2h<<<(n8 + 255) / 256, 256>>>(q, qi, n8);
    cvt_f2h<<<(n8 + 255) / 256, 256>>>(k, ki, n8);
    cvt_f2h<<<(n8 + 255) / 256, 256>>>(v, vi, n8);
    dim3 wGrid(DM / 32, DM / 32), wThr(32, 8);
    cvt_wT<<<wGrid, wThr>>>(Wq, Wqt);
    cvt_wT<<<wGrid, wThr>>>(Wk, Wkt);
    cvt_wT<<<wGrid, wThr>>>(Wv, Wvt);
    cvt_wT<<<wGrid, wThr>>>(Wo, Wot);

    dim3 gGrid(DM / 128, MTOT / 128);

    // projections: Q (rope+scale), K (rope), V
    gemm_f16<1><<<gGrid, 256>>>(qi, Wqt, Qh);
    gemm_f16<2><<<gGrid, 256>>>(ki, Wkt, Kh);
    gemm_f16<3><<<gGrid, 256>>>(vi, Wvt, Vh);

    // flash attention
    dim3 aGrid(SS / 128, NH, BB);
    flash_f16<<<aGrid, 256>>>(Qh, Kh, Vh, Ch);

    // output projection (fp16 MMA, fp32 out)
    gemm_f16<0><<<gGrid, 256>>>(Ch, Wot, out);
}

// round 8
// speedup vs baseline: 2.2550x; 1.0918x over previous
#include <cuda_runtime.h>
#include <cuda_fp16.h>
#include <math.h>

#define BB 4
#define SS 2048
#define DM 1024
#define NH 16
#define DK 64
#define MTOT (BB*SS)

// scratch (device globals; allocation-free at launch time)
__device__ __half g_qi[(size_t)MTOT*DM];
__device__ __half g_ki[(size_t)MTOT*DM];
__device__ __half g_vi[(size_t)MTOT*DM];
__device__ __half g_Wqt[(size_t)DM*DM];
__device__ __half g_Wkt[(size_t)DM*DM];
__device__ __half g_Wvt[(size_t)DM*DM];
__device__ __half g_Wot[(size_t)DM*DM];
__device__ __half g_Qh[(size_t)MTOT*DM];
__device__ __half g_Kh[(size_t)MTOT*DM];
__device__ __half g_Vh[(size_t)MTOT*DM];
__device__ __half g_Ch[(size_t)MTOT*DM];

// ---------------------------------------------------------------------------
// helpers
// ---------------------------------------------------------------------------
__device__ __forceinline__ void mma_f16(float c[4],
                                        unsigned a0, unsigned a1, unsigned a2, unsigned a3,
                                        unsigned b0, unsigned b1) {
    asm volatile(
        "mma.sync.aligned.m16n8k16.row.col.f32.f16.f16.f32 "
        "{%0,%1,%2,%3},{%4,%5,%6,%7},{%8,%9},{%0,%1,%2,%3};"
        : "+f"(c[0]), "+f"(c[1]), "+f"(c[2]), "+f"(c[3])
        : "r"(a0), "r"(a1), "r"(a2), "r"(a3), "r"(b0), "r"(b1));
}

__device__ __forceinline__ unsigned sptr(const void* p) {
    return (unsigned)__cvta_generic_to_shared(p);
}

__device__ __forceinline__ void ldsm_x4(unsigned& r0, unsigned& r1,
                                        unsigned& r2, unsigned& r3, unsigned a) {
    asm volatile("ldmatrix.sync.aligned.m8n8.x4.shared.b16 {%0,%1,%2,%3}, [%4];"
                 : "=r"(r0), "=r"(r1), "=r"(r2), "=r"(r3) : "r"(a));
}

__device__ __forceinline__ void ldsm_x4t(unsigned& r0, unsigned& r1,
                                         unsigned& r2, unsigned& r3, unsigned a) {
    asm volatile("ldmatrix.sync.aligned.m8n8.x4.trans.shared.b16 {%0,%1,%2,%3}, [%4];"
                 : "=r"(r0), "=r"(r1), "=r"(r2), "=r"(r3) : "r"(a));
}

__device__ __forceinline__ unsigned packh2(float a, float b) {
    __half2 h = __floats2half2_rn(a, b);
    return *(unsigned*)&h;
}

__device__ __forceinline__ void cp16(void* dst_smem, const void* src_gmem) {
    unsigned s = (unsigned)__cvta_generic_to_shared(dst_smem);
    asm volatile("cp.async.cg.shared.global [%0], [%1], 16;" :: "r"(s), "l"(src_gmem));
}
__device__ __forceinline__ void cp_commit() { asm volatile("cp.async.commit_group;"); }
template<int N> __device__ __forceinline__ void cp_wait() {
    asm volatile("cp.async.wait_group %0;" :: "n"(N));
}

// log2(10000)/32
#define ROPE_L2 0.41524101186f

// ---------------------------------------------------------------------------
// converts
// ---------------------------------------------------------------------------
__global__ void cvt_f2h(const float* __restrict__ X, __half* __restrict__ Y, int n8) {
    int i = blockIdx.x * blockDim.x + threadIdx.x;
    if (i >= n8) return;
    const float4 v0 = *(const float4*)(X + (size_t)i * 8);
    const float4 v1 = *(const float4*)(X + (size_t)i * 8 + 4);
    __half2 h[4] = {__floats2half2_rn(v0.x, v0.y), __floats2half2_rn(v0.z, v0.w),
                    __floats2half2_rn(v1.x, v1.y), __floats2half2_rn(v1.z, v1.w)};
    *(uint4*)(Y + (size_t)i * 8) = *(uint4*)h;
}

// W [K][N] fp32 -> Wt [N][K] fp16
__global__ void cvt_wT(const float* __restrict__ W, __half* __restrict__ Wt) {
    __shared__ float t[32][33];
    const int bn = blockIdx.x * 32, bk = blockIdx.y * 32;
    const int x = threadIdx.x, y = threadIdx.y;
    #pragma unroll
    for (int i = 0; i < 32; i += 8)
        t[y + i][x] = W[(size_t)(bk + y + i) * DM + bn + x];
    __syncthreads();
    #pragma unroll
    for (int i = 0; i < 32; i += 8)
        Wt[(size_t)(bn + y + i) * DM + bk + x] = __float2half(t[x][y + i]);
}

// ---------------------------------------------------------------------------
// FP16 GEMM: C[M,N] = A[M,K] * Bt[N,K]^T. BM=BN=128, BK=32, 256 thr = 8 warps
// (4x2), warp tile 32x64 via m16n8k16, fragments via ldmatrix.
// MODE: 0 = fp32 store; 1 = rope + 0.125 scale + half; 2 = rope + half; 3 = half.
// ---------------------------------------------------------------------------
template<int MODE>
__global__ __launch_bounds__(256) void gemm_f16(const __half* __restrict__ A,
                                                const __half* __restrict__ Bt,
                                                void* __restrict__ Cout) {
    __shared__ __half As[2][128][40];
    __shared__ __half Bs[2][128][40];

    const int tid  = threadIdx.x;
    const int wid  = tid >> 5;
    const int lane = tid & 31;
    const int g    = lane >> 2;
    const int tig  = lane & 3;
    const int rw   = wid >> 1;
    const int cw   = wid & 1;
    const int m0   = blockIdx.y * 128;
    const int n0b  = blockIdx.x * 128;

    const int lr = tid >> 1;
    const int lc = (tid & 1) * 16;

    // ldmatrix lane-row offsets (within-warp)
    const int aRow = lane & 15;                 // A/V style: rows, col step by l>>4
    const int aCol = 8 * (lane >> 4);
    const int bRow = 8 * (lane >> 4) + (lane & 7);   // B/K style
    const int bCol = 8 * ((lane >> 3) & 1);

    float acc[2][8][4];
    #pragma unroll
    for (int i = 0; i < 2; i++)
        #pragma unroll
        for (int j = 0; j < 8; j++)
            #pragma unroll
            for (int l = 0; l < 4; l++) acc[i][j][l] = 0.0f;

    const __half* asrc = A  + (size_t)(m0  + lr) * DM + lc;
    const __half* bsrc = Bt + (size_t)(n0b + lr) * DM + lc;

    cp16(&As[0][lr][lc],     asrc);
    cp16(&As[0][lr][lc + 8], asrc + 8);
    cp16(&Bs[0][lr][lc],     bsrc);
    cp16(&Bs[0][lr][lc + 8], bsrc + 8);
    cp_commit();

    const int NT = DM / 32;
    for (int t = 0; t < NT; t++) {
        const int buf = t & 1;
        if (t + 1 < NT) {
            const __half* a2 = asrc + (t + 1) * 32;
            const __half* b2 = bsrc + (t + 1) * 32;
            cp16(&As[buf ^ 1][lr][lc],     a2);
            cp16(&As[buf ^ 1][lr][lc + 8], a2 + 8);
            cp16(&Bs[buf ^ 1][lr][lc],     b2);
            cp16(&Bs[buf ^ 1][lr][lc + 8], b2 + 8);
            cp_commit();
            cp_wait<1>();
        } else {
            cp_wait<0>();
        }
        __syncthreads();

        #pragma unroll
        for (int kb = 0; kb < 2; kb++) {
            const int kk = kb * 16;
            unsigned a[2][4];
            #pragma unroll
            for (int mt = 0; mt < 2; mt++) {
                const int r = rw * 32 + mt * 16;
                ldsm_x4(a[mt][0], a[mt][1], a[mt][2], a[mt][3],
                        sptr(&As[buf][r + aRow][kk + aCol]));
            }
            unsigned b[8][2];
            #pragma unroll
            for (int ntp = 0; ntp < 4; ntp++) {
                const int n0 = cw * 64 + ntp * 16;
                ldsm_x4(b[2 * ntp][0], b[2 * ntp][1], b[2 * ntp + 1][0], b[2 * ntp + 1][1],
                        sptr(&Bs[buf][n0 + bRow][kk + bCol]));
            }
            #pragma unroll
            for (int mt = 0; mt < 2; mt++)
                #pragma unroll
                for (int nt = 0; nt < 8; nt++)
                    mma_f16(acc[mt][nt], a[mt][0], a[mt][1], a[mt][2], a[mt][3],
                            b[nt][0], b[nt][1]);
        }
        __syncthreads();
    }

    #pragma unroll
    for (int mt = 0; mt < 2; mt++) {
        const int r = m0 + rw * 32 + mt * 16 + g;
        const int pos0 = r & (SS - 1);
        const int pos8 = (r + 8) & (SS - 1);
        #pragma unroll
        for (int nt = 0; nt < 8; nt++) {
            const int c = n0b + cw * 64 + nt * 8 + 2 * tig;
            float y0 = acc[mt][nt][0], y1 = acc[mt][nt][1];
            float y2 = acc[mt][nt][2], y3 = acc[mt][nt][3];
            if (MODE == 1 || MODE == 2) {
                const int i = (c & 63) >> 1;
                const float inv = exp2f(-(float)i * ROPE_L2);
                float s0, c0, s8, c8;
                sincosf((float)pos0 * inv, &s0, &c0);
                sincosf((float)pos8 * inv, &s8, &c8);
                float x1 = y0, x2 = y1;
                y0 = x1 * c0 - x2 * s0;
                y1 = x1 * s0 + x2 * c0;
                x1 = y2; x2 = y3;
                y2 = x1 * c8 - x2 * s8;
                y3 = x1 * s8 + x2 * c8;
            }
            if (MODE == 1) { y0 *= 0.125f; y1 *= 0.125f; y2 *= 0.125f; y3 *= 0.125f; }
            if (MODE == 0) {
                float* C = (float*)Cout;
                *(float2*)&C[(size_t)r * DM + c]       = make_float2(y0, y1);
                *(float2*)&C[(size_t)(r + 8) * DM + c] = make_float2(y2, y3);
            } else {
                __half* C = (__half*)Cout;
                *(__half2*)&C[(size_t)r * DM + c]       = __floats2half2_rn(y0, y1);
                *(__half2*)&C[(size_t)(r + 8) * DM + c] = __floats2half2_rn(y2, y3);
            }
        }
    }
}

// ---------------------------------------------------------------------------
// Flash attention, fp16 MMA + ldmatrix. BM=128, BN=64, DK=64.
// 256 threads = 8 warps x 16 q rows. Q/P fragments in registers; K via
// ldmatrix.x4, V via ldmatrix.x4.trans (zero packing ALU).
// ---------------------------------------------------------------------------
__global__ __launch_bounds__(256, 2) void flash_f16(const __half* __restrict__ Qh,
                                                    const __half* __restrict__ Kh,
                                                    const __half* __restrict__ Vh,
                                                    __half* __restrict__ O) {
    __shared__ __half Ks[2][64][72];
    __shared__ __half Vs[2][64][72];

    const int tid  = threadIdx.x;
    const int wid  = tid >> 5;
    const int lane = tid & 31;
    const int g    = lane >> 2;
    const int tig  = lane & 3;
    const int h    = blockIdx.y;
    const int b    = blockIdx.z;
    const int q0   = wid * 16;
    const size_t qbase = ((size_t)b * SS + blockIdx.x * 128) * DM + h * DK;
    const size_t kvbase = (size_t)b * SS * DM + h * DK;

    const int bRow = 8 * (lane >> 4) + (lane & 7);   // K ldmatrix rows
    const int bCol = 8 * ((lane >> 3) & 1);
    const int vRow = lane & 15;                      // V ldmatrix rows
    const int vCol = 8 * (lane >> 4);

    unsigned qf[4][4];
    {
        const __half* q_r0 = Qh + qbase + (size_t)(q0 + g) * DM;
        const __half* q_r8 = Qh + qbase + (size_t)(q0 + g + 8) * DM;
        #pragma unroll
        for (int kb = 0; kb < 4; kb++) {
            const int cc = kb * 16 + 2 * tig;
            qf[kb][0] = *(const unsigned*)(q_r0 + cc);
            qf[kb][1] = *(const unsigned*)(q_r8 + cc);
            qf[kb][2] = *(const unsigned*)(q_r0 + cc + 8);
            qf[kb][3] = *(const unsigned*)(q_r8 + cc + 8);
        }
    }

    const int pr = tid >> 2;
    const int pc = (tid & 3) * 16;
    auto kv_prefetch = [&](int kt, int buf) {
        const __half* ksrc = Kh + kvbase + ((size_t)kt * 64 + pr) * DM + pc;
        const __half* vsrc = Vh + kvbase + ((size_t)kt * 64 + pr) * DM + pc;
        cp16(&Ks[buf][pr][pc],     ksrc);
        cp16(&Ks[buf][pr][pc + 8], ksrc + 8);
        cp16(&Vs[buf][pr][pc],     vsrc);
        cp16(&Vs[buf][pr][pc + 8], vsrc + 8);
        cp_commit();
    };

    kv_prefetch(0, 0);

    float o[8][4];
    #pragma unroll
    for (int nt = 0; nt < 8; nt++)
        #pragma unroll
        for (int j = 0; j < 4; j++) o[nt][j] = 0.0f;
    float mrow0 = -INFINITY, mrow1 = -INFINITY;
    float lrow0 = 0.0f, lrow1 = 0.0f;

    const int NKT = SS / 64;
    for (int kt = 0; kt < NKT; kt++) {
        const int buf = kt & 1;
        __syncthreads();
        if (kt + 1 < NKT) {
            kv_prefetch(kt + 1, buf ^ 1);
            cp_wait<1>();
        } else {
            cp_wait<0>();
        }
        __syncthreads();

        // S = (Q/8) K^T -- K b-frags via ldmatrix.x4
        float s[8][4];
        #pragma unroll
        for (int nt = 0; nt < 8; nt++)
            #pragma unroll
            for (int j = 0; j < 4; j++) s[nt][j] = 0.0f;

        #pragma unroll
        for (int kb = 0; kb < 4; kb++) {
            const int kk = kb * 16;
            #pragma unroll
            for (int ntp = 0; ntp < 4; ntp++) {
                const int n0 = ntp * 16;
                unsigned b0a, b1a, b0b, b1b;
                ldsm_x4(b0a, b1a, b0b, b1b, sptr(&Ks[buf][n0 + bRow][kk + bCol]));
                mma_f16(s[2 * ntp],     qf[kb][0], qf[kb][1], qf[kb][2], qf[kb][3], b0a, b1a);
                mma_f16(s[2 * ntp + 1], qf[kb][0], qf[kb][1], qf[kb][2], qf[kb][3], b0b, b1b);
            }
        }

        // online softmax
        float mx0 = -INFINITY, mx1 = -INFINITY;
        #pragma unroll
        for (int nt = 0; nt < 8; nt++) {
            mx0 = fmaxf(mx0, fmaxf(s[nt][0], s[nt][1]));
            mx1 = fmaxf(mx1, fmaxf(s[nt][2], s[nt][3]));
        }
        mx0 = fmaxf(mx0, __shfl_xor_sync(0xffffffffu, mx0, 1));
        mx0 = fmaxf(mx0, __shfl_xor_sync(0xffffffffu, mx0, 2));
        mx1 = fmaxf(mx1, __shfl_xor_sync(0xffffffffu, mx1, 1));
        mx1 = fmaxf(mx1, __shfl_xor_sync(0xffffffffu, mx1, 2));

        const float mn0 = fmaxf(mrow0, mx0);
        const float mn1 = fmaxf(mrow1, mx1);
        const float f0 = __expf(mrow0 - mn0);
        const float f1 = __expf(mrow1 - mn1);
        mrow0 = mn0; mrow1 = mn1;

        unsigned ph[8][2];
        float sum0 = 0.0f, sum1 = 0.0f;
        #pragma unroll
        for (int nt = 0; nt < 8; nt++) {
            float p0 = __expf(s[nt][0] - mn0);
            float p1 = __expf(s[nt][1] - mn0);
            float p2 = __expf(s[nt][2] - mn1);
            float p3 = __expf(s[nt][3] - mn1);
            sum0 += p0 + p1;
            sum1 += p2 + p3;
            ph[nt][0] = packh2(p0, p1);
            ph[nt][1] = packh2(p2, p3);
        }
        sum0 += __shfl_xor_sync(0xffffffffu, sum0, 1);
        sum0 += __shfl_xor_sync(0xffffffffu, sum0, 2);
        sum1 += __shfl_xor_sync(0xffffffffu, sum1, 1);
        sum1 += __shfl_xor_sync(0xffffffffu, sum1, 2);
        lrow0 = lrow0 * f0 + sum0;
        lrow1 = lrow1 * f1 + sum1;

        #pragma unroll
        for (int nt = 0; nt < 8; nt++) {
            o[nt][0] *= f0; o[nt][1] *= f0;
            o[nt][2] *= f1; o[nt][3] *= f1;
        }

        // O += P V -- V b-frags via ldmatrix.x4.trans
        #pragma unroll
        for (int kb = 0; kb < 4; kb++) {
            const int k0i = kb * 16;
            const unsigned a0 = ph[2 * kb][0];
            const unsigned a1 = ph[2 * kb][1];
            const unsigned a2 = ph[2 * kb + 1][0];
            const unsigned a3 = ph[2 * kb + 1][1];
            #pragma unroll
            for (int dtp = 0; dtp < 4; dtp++) {
                const int d0 = dtp * 16;
                unsigned v0a, v1a, v0b, v1b;
                ldsm_x4t(v0a, v1a, v0b, v1b, sptr(&Vs[buf][k0i + vRow][d0 + vCol]));
                mma_f16(o[2 * dtp],     a0, a1, a2, a3, v0a, v1a);
                mma_f16(o[2 * dtp + 1], a0, a1, a2, a3, v0b, v1b);
            }
        }
    }

    const float inv0 = 1.0f / lrow0;
    const float inv1 = 1.0f / lrow1;
    #pragma unroll
    for (int nt = 0; nt < 8; nt++) {
        const int c = nt * 8 + 2 * tig;
        *(__half2*)&O[qbase + (size_t)(q0 + g) * DM + c] =
            __floats2half2_rn(o[nt][0] * inv0, o[nt][1] * inv0);
        *(__half2*)&O[qbase + (size_t)(q0 + g + 8) * DM + c] =
            __floats2half2_rn(o[nt][2] * inv1, o[nt][3] * inv1);
    }
}

// ---------------------------------------------------------------------------
extern "C" void kernel_launch(void* const* d_in, const int* in_sizes, int n_in,
                              void* d_out, int out_size) {
    const float* q  = (const float*)d_in[0];
    const float* k  = (const float*)d_in[1];
    const float* v  = (const float*)d_in[2];
    const float* Wq = (const float*)d_in[3];
    const float* Wk = (const float*)d_in[4];
    const float* Wv = (const float*)d_in[5];
    const float* Wo = (const float*)d_in[6];
    float* out = (float*)d_out;

    __half *qi, *ki, *vi, *Wqt, *Wkt, *Wvt, *Wot, *Qh, *Kh, *Vh, *Ch;
    cudaGetSymbolAddress((void**)&qi,  g_qi);
    cudaGetSymbolAddress((void**)&ki,  g_ki);
    cudaGetSymbolAddress((void**)&vi,  g_vi);
    cudaGetSymbolAddress((void**)&Wqt, g_Wqt);
    cudaGetSymbolAddress((void**)&Wkt, g_Wkt);
    cudaGetSymbolAddress((void**)&Wvt, g_Wvt);
    cudaGetSymbolAddress((void**)&Wot, g_Wot);
    cudaGetSymbolAddress((void**)&Qh,  g_Qh);
    cudaGetSymbolAddress((void**)&Kh,  g_Kh);
    cudaGetSymbolAddress((void**)&Vh,  g_Vh);
    cudaGetSymbolAddress((void**)&Ch,  g_Ch);

    const int n8 = MTOT * DM / 8;
    cvt_f2h<<<(n8 + 255) / 256, 256>>>(q, qi, n8);
    cvt_f2h<<<(n8 + 255) / 256, 256>>>(k, ki, n8);
    cvt_f2h<<<(n8 + 255) / 256, 256>>>(v, vi, n8);
    dim3 wGrid(DM / 32, DM / 32), wThr(32, 8);
    cvt_wT<<<wGrid, wThr>>>(Wq, Wqt);
    cvt_wT<<<wGrid, wThr>>>(Wk, Wkt);
    cvt_wT<<<wGrid, wThr>>>(Wv, Wvt);
    cvt_wT<<<wGrid, wThr>>>(Wo, Wot);

    dim3 gGrid(DM / 128, MTOT / 128);

    gemm_f16<1><<<gGrid, 256>>>(qi, Wqt, Qh);
    gemm_f16<2><<<gGrid, 256>>>(ki, Wkt, Kh);
    gemm_f16<3><<<gGrid, 256>>>(vi, Wvt, Vh);

    dim3 aGrid(SS / 128, NH, BB);
    flash_f16<<<aGrid, 256>>>(Qh, Kh, Vh, Ch);

    gemm_f16<0><<<gGrid, 256>>>(Ch, Wot, out);
}

// round 9
// speedup vs baseline: 2.3721x; 1.0520x over previous
#include <cuda_runtime.h>
#include <cuda_fp16.h>
#include <math.h>

#define BB 4
#define SS 2048
#define DM 1024
#define NH 16
#define DK 64
#define MTOT (BB*SS)

// scratch (device globals; allocation-free at launch time)
__device__ __half g_qi[(size_t)MTOT*DM];
__device__ __half g_ki[(size_t)MTOT*DM];
__device__ __half g_vi[(size_t)MTOT*DM];
__device__ __half g_Wqt[(size_t)DM*DM];
__device__ __half g_Wkt[(size_t)DM*DM];
__device__ __half g_Wvt[(size_t)DM*DM];
__device__ __half g_Wot[(size_t)DM*DM];
__device__ __half g_Qh[(size_t)MTOT*DM];
__device__ __half g_Kh[(size_t)MTOT*DM];
__device__ __half g_Vh[(size_t)MTOT*DM];
__device__ __half g_Ch[(size_t)MTOT*DM];

// ---------------------------------------------------------------------------
// helpers
// ---------------------------------------------------------------------------
__device__ __forceinline__ void mma_f16(float c[4],
                                        unsigned a0, unsigned a1, unsigned a2, unsigned a3,
                                        unsigned b0, unsigned b1) {
    asm volatile(
        "mma.sync.aligned.m16n8k16.row.col.f32.f16.f16.f32 "
        "{%0,%1,%2,%3},{%4,%5,%6,%7},{%8,%9},{%0,%1,%2,%3};"
        : "+f"(c[0]), "+f"(c[1]), "+f"(c[2]), "+f"(c[3])
        : "r"(a0), "r"(a1), "r"(a2), "r"(a3), "r"(b0), "r"(b1));
}

__device__ __forceinline__ unsigned sptr(const void* p) {
    return (unsigned)__cvta_generic_to_shared(p);
}

__device__ __forceinline__ void ldsm_x4(unsigned& r0, unsigned& r1,
                                        unsigned& r2, unsigned& r3, unsigned a) {
    asm volatile("ldmatrix.sync.aligned.m8n8.x4.shared.b16 {%0,%1,%2,%3}, [%4];"
                 : "=r"(r0), "=r"(r1), "=r"(r2), "=r"(r3) : "r"(a));
}

__device__ __forceinline__ void ldsm_x4t(unsigned& r0, unsigned& r1,
                                         unsigned& r2, unsigned& r3, unsigned a) {
    asm volatile("ldmatrix.sync.aligned.m8n8.x4.trans.shared.b16 {%0,%1,%2,%3}, [%4];"
                 : "=r"(r0), "=r"(r1), "=r"(r2), "=r"(r3) : "r"(a));
}

__device__ __forceinline__ unsigned packh2(float a, float b) {
    __half2 h = __floats2half2_rn(a, b);
    return *(unsigned*)&h;
}

__device__ __forceinline__ void cp16(void* dst_smem, const void* src_gmem) {
    unsigned s = (unsigned)__cvta_generic_to_shared(dst_smem);
    asm volatile("cp.async.cg.shared.global [%0], [%1], 16;" :: "r"(s), "l"(src_gmem));
}
__device__ __forceinline__ void cp_commit() { asm volatile("cp.async.commit_group;"); }
template<int N> __device__ __forceinline__ void cp_wait() {
    asm volatile("cp.async.wait_group %0;" :: "n"(N));
}

// log2(10000)/32
#define ROPE_L2 0.41524101186f

// ---------------------------------------------------------------------------
// converts
// ---------------------------------------------------------------------------
__global__ void cvt3_f2h(const float* __restrict__ q, const float* __restrict__ k,
                         const float* __restrict__ v,
                         __half* __restrict__ qo, __half* __restrict__ ko,
                         __half* __restrict__ vo, int n8) {
    const float* X;
    __half* Y;
    if (blockIdx.y == 0)      { X = q; Y = qo; }
    else if (blockIdx.y == 1) { X = k; Y = ko; }
    else                      { X = v; Y = vo; }
    int i = blockIdx.x * blockDim.x + threadIdx.x;
    if (i >= n8) return;
    const float4 v0 = *(const float4*)(X + (size_t)i * 8);
    const float4 v1 = *(const float4*)(X + (size_t)i * 8 + 4);
    __half2 h[4] = {__floats2half2_rn(v0.x, v0.y), __floats2half2_rn(v0.z, v0.w),
                    __floats2half2_rn(v1.x, v1.y), __floats2half2_rn(v1.z, v1.w)};
    *(uint4*)(Y + (size_t)i * 8) = *(uint4*)h;
}

// W [K][N] fp32 -> Wt [N][K] fp16
__global__ void cvt_wT(const float* __restrict__ W, __half* __restrict__ Wt) {
    __shared__ float t[32][33];
    const int bn = blockIdx.x * 32, bk = blockIdx.y * 32;
    const int x = threadIdx.x, y = threadIdx.y;
    #pragma unroll
    for (int i = 0; i < 32; i += 8)
        t[y + i][x] = W[(size_t)(bk + y + i) * DM + bn + x];
    __syncthreads();
    #pragma unroll
    for (int i = 0; i < 32; i += 8)
        Wt[(size_t)(bn + y + i) * DM + bk + x] = __float2half(t[x][y + i]);
}

// ---------------------------------------------------------------------------
// FP16 GEMM: C[M,N] = A[M,K] * Bt[N,K]^T. BM=BN=128, BK=32, 256 thr = 8 warps
// (4x2), warp tile 32x64, ldmatrix frags, 3-stage cp.async, 1 sync/iter.
// MODE: 0 = fp32 store; 1 = rope + 0.125 scale + half; 2 = rope + half; 3 = half.
// ---------------------------------------------------------------------------
#define GS 3
template<int MODE>
__global__ __launch_bounds__(256) void gemm_f16(const __half* __restrict__ A,
                                                const __half* __restrict__ Bt,
                                                void* __restrict__ Cout) {
    extern __shared__ __half gsm[];
    __half (*As)[128][40] = (__half(*)[128][40])gsm;                    // [GS]
    __half (*Bs)[128][40] = (__half(*)[128][40])(gsm + GS * 128 * 40);  // [GS]

    const int tid  = threadIdx.x;
    const int wid  = tid >> 5;
    const int lane = tid & 31;
    const int g    = lane >> 2;
    const int tig  = lane & 3;
    const int rw   = wid >> 1;
    const int cw   = wid & 1;
    const int m0   = blockIdx.y * 128;
    const int n0b  = blockIdx.x * 128;

    const int lr = tid >> 1;
    const int lc = (tid & 1) * 16;

    const int aRow = lane & 15;
    const int aCol = 8 * (lane >> 4);
    const int bRow = 8 * (lane >> 4) + (lane & 7);
    const int bCol = 8 * ((lane >> 3) & 1);

    float acc[2][8][4];
    #pragma unroll
    for (int i = 0; i < 2; i++)
        #pragma unroll
        for (int j = 0; j < 8; j++)
            #pragma unroll
            for (int l = 0; l < 4; l++) acc[i][j][l] = 0.0f;

    const __half* asrc = A  + (size_t)(m0  + lr) * DM + lc;
    const __half* bsrc = Bt + (size_t)(n0b + lr) * DM + lc;

    // prefetch stages 0..GS-2
    #pragma unroll
    for (int p = 0; p < GS - 1; p++) {
        cp16(&As[p][lr][lc],     asrc + p * 32);
        cp16(&As[p][lr][lc + 8], asrc + p * 32 + 8);
        cp16(&Bs[p][lr][lc],     bsrc + p * 32);
        cp16(&Bs[p][lr][lc + 8], bsrc + p * 32 + 8);
        cp_commit();
    }

    const int NT = DM / 32;
    int buf = 0, wbuf = GS - 1;
    for (int t = 0; t < NT; t++) {
        cp_wait<GS - 2>();
        __syncthreads();

        // issue load for tile t+GS-1 (overlaps with compute below)
        if (t + GS - 1 < NT) {
            const __half* a2 = asrc + (t + GS - 1) * 32;
            const __half* b2 = bsrc + (t + GS - 1) * 32;
            cp16(&As[wbuf][lr][lc],     a2);
            cp16(&As[wbuf][lr][lc + 8], a2 + 8);
            cp16(&Bs[wbuf][lr][lc],     b2);
            cp16(&Bs[wbuf][lr][lc + 8], b2 + 8);
        }
        cp_commit();   // commit (possibly empty) group to keep wait counts aligned

        #pragma unroll
        for (int kb = 0; kb < 2; kb++) {
            const int kk = kb * 16;
            unsigned a[2][4];
            #pragma unroll
            for (int mt = 0; mt < 2; mt++) {
                const int r = rw * 32 + mt * 16;
                ldsm_x4(a[mt][0], a[mt][1], a[mt][2], a[mt][3],
                        sptr(&As[buf][r + aRow][kk + aCol]));
            }
            unsigned b[8][2];
            #pragma unroll
            for (int ntp = 0; ntp < 4; ntp++) {
                const int n0 = cw * 64 + ntp * 16;
                ldsm_x4(b[2 * ntp][0], b[2 * ntp][1], b[2 * ntp + 1][0], b[2 * ntp + 1][1],
                        sptr(&Bs[buf][n0 + bRow][kk + bCol]));
            }
            #pragma unroll
            for (int mt = 0; mt < 2; mt++)
                #pragma unroll
                for (int nt = 0; nt < 8; nt++)
                    mma_f16(acc[mt][nt], a[mt][0], a[mt][1], a[mt][2], a[mt][3],
                            b[nt][0], b[nt][1]);
        }
        buf  = (buf  + 1 == GS) ? 0 : buf + 1;
        wbuf = (wbuf + 1 == GS) ? 0 : wbuf + 1;
    }

    #pragma unroll
    for (int mt = 0; mt < 2; mt++) {
        const int r = m0 + rw * 32 + mt * 16 + g;
        const int pos0 = r & (SS - 1);
        const int pos8 = (r + 8) & (SS - 1);
        #pragma unroll
        for (int nt = 0; nt < 8; nt++) {
            const int c = n0b + cw * 64 + nt * 8 + 2 * tig;
            float y0 = acc[mt][nt][0], y1 = acc[mt][nt][1];
            float y2 = acc[mt][nt][2], y3 = acc[mt][nt][3];
            if (MODE == 1 || MODE == 2) {
                const int i = (c & 63) >> 1;
                const float inv = exp2f(-(float)i * ROPE_L2);
                float s0, c0, s8, c8;
                sincosf((float)pos0 * inv, &s0, &c0);
                sincosf((float)pos8 * inv, &s8, &c8);
                float x1 = y0, x2 = y1;
                y0 = x1 * c0 - x2 * s0;
                y1 = x1 * s0 + x2 * c0;
                x1 = y2; x2 = y3;
                y2 = x1 * c8 - x2 * s8;
                y3 = x1 * s8 + x2 * c8;
            }
            if (MODE == 1) { y0 *= 0.125f; y1 *= 0.125f; y2 *= 0.125f; y3 *= 0.125f; }
            if (MODE == 0) {
                float* C = (float*)Cout;
                *(float2*)&C[(size_t)r * DM + c]       = make_float2(y0, y1);
                *(float2*)&C[(size_t)(r + 8) * DM + c] = make_float2(y2, y3);
            } else {
                __half* C = (__half*)Cout;
                *(__half2*)&C[(size_t)r * DM + c]       = __floats2half2_rn(y0, y1);
                *(__half2*)&C[(size_t)(r + 8) * DM + c] = __floats2half2_rn(y2, y3);
            }
        }
    }
}

// ---------------------------------------------------------------------------
// Flash attention, fp16 MMA + ldmatrix, 3-stage cp.async, 1 sync/iter.
// BM=128, BN=64, DK=64. 256 threads = 8 warps x 16 q rows.
// ---------------------------------------------------------------------------
#define FS 3
__global__ __launch_bounds__(256, 2) void flash_f16(const __half* __restrict__ Qh,
                                                    const __half* __restrict__ Kh,
                                                    const __half* __restrict__ Vh,
                                                    __half* __restrict__ O) {
    extern __shared__ __half fsm[];
    __half (*Ks)[64][72] = (__half(*)[64][72])fsm;                   // [FS]
    __half (*Vs)[64][72] = (__half(*)[64][72])(fsm + FS * 64 * 72);  // [FS]

    const int tid  = threadIdx.x;
    const int wid  = tid >> 5;
    const int lane = tid & 31;
    const int g    = lane >> 2;
    const int tig  = lane & 3;
    const int h    = blockIdx.y;
    const int b    = blockIdx.z;
    const int q0   = wid * 16;
    const size_t qbase = ((size_t)b * SS + blockIdx.x * 128) * DM + h * DK;
    const size_t kvbase = (size_t)b * SS * DM + h * DK;

    const int bRow = 8 * (lane >> 4) + (lane & 7);
    const int bCol = 8 * ((lane >> 3) & 1);
    const int vRow = lane & 15;
    const int vCol = 8 * (lane >> 4);

    unsigned qf[4][4];
    {
        const __half* q_r0 = Qh + qbase + (size_t)(q0 + g) * DM;
        const __half* q_r8 = Qh + qbase + (size_t)(q0 + g + 8) * DM;
        #pragma unroll
        for (int kb = 0; kb < 4; kb++) {
            const int cc = kb * 16 + 2 * tig;
            qf[kb][0] = *(const unsigned*)(q_r0 + cc);
            qf[kb][1] = *(const unsigned*)(q_r8 + cc);
            qf[kb][2] = *(const unsigned*)(q_r0 + cc + 8);
            qf[kb][3] = *(const unsigned*)(q_r8 + cc + 8);
        }
    }

    const int pr = tid >> 2;
    const int pc = (tid & 3) * 16;
    auto kv_issue = [&](int kt, int buf) {
        const __half* ksrc = Kh + kvbase + ((size_t)kt * 64 + pr) * DM + pc;
        const __half* vsrc = Vh + kvbase + ((size_t)kt * 64 + pr) * DM + pc;
        cp16(&Ks[buf][pr][pc],     ksrc);
        cp16(&Ks[buf][pr][pc + 8], ksrc + 8);
        cp16(&Vs[buf][pr][pc],     vsrc);
        cp16(&Vs[buf][pr][pc + 8], vsrc + 8);
    };

    #pragma unroll
    for (int p = 0; p < FS - 1; p++) { kv_issue(p, p); cp_commit(); }

    float o[8][4];
    #pragma unroll
    for (int nt = 0; nt < 8; nt++)
        #pragma unroll
        for (int j = 0; j < 4; j++) o[nt][j] = 0.0f;
    float mrow0 = -INFINITY, mrow1 = -INFINITY;
    float lrow0 = 0.0f, lrow1 = 0.0f;

    const int NKT = SS / 64;
    int buf = 0, wbuf = FS - 1;
    for (int kt = 0; kt < NKT; kt++) {
        cp_wait<FS - 2>();
        __syncthreads();

        if (kt + FS - 1 < NKT) kv_issue(kt + FS - 1, wbuf);
        cp_commit();

        // S = (Q/8) K^T
        float s[8][4];
        #pragma unroll
        for (int nt = 0; nt < 8; nt++)
            #pragma unroll
            for (int j = 0; j < 4; j++) s[nt][j] = 0.0f;

        #pragma unroll
        for (int kb = 0; kb < 4; kb++) {
            const int kk = kb * 16;
            #pragma unroll
            for (int ntp = 0; ntp < 4; ntp++) {
                const int n0 = ntp * 16;
                unsigned b0a, b1a, b0b, b1b;
                ldsm_x4(b0a, b1a, b0b, b1b, sptr(&Ks[buf][n0 + bRow][kk + bCol]));
                mma_f16(s[2 * ntp],     qf[kb][0], qf[kb][1], qf[kb][2], qf[kb][3], b0a, b1a);
                mma_f16(s[2 * ntp + 1], qf[kb][0], qf[kb][1], qf[kb][2], qf[kb][3], b0b, b1b);
            }
        }

        // online softmax
        float mx0 = -INFINITY, mx1 = -INFINITY;
        #pragma unroll
        for (int nt = 0; nt < 8; nt++) {
            mx0 = fmaxf(mx0, fmaxf(s[nt][0], s[nt][1]));
            mx1 = fmaxf(mx1, fmaxf(s[nt][2], s[nt][3]));
        }
        mx0 = fmaxf(mx0, __shfl_xor_sync(0xffffffffu, mx0, 1));
        mx0 = fmaxf(mx0, __shfl_xor_sync(0xffffffffu, mx0, 2));
        mx1 = fmaxf(mx1, __shfl_xor_sync(0xffffffffu, mx1, 1));
        mx1 = fmaxf(mx1, __shfl_xor_sync(0xffffffffu, mx1, 2));

        const float mn0 = fmaxf(mrow0, mx0);
        const float mn1 = fmaxf(mrow1, mx1);
        const float f0 = __expf(mrow0 - mn0);
        const float f1 = __expf(mrow1 - mn1);
        mrow0 = mn0; mrow1 = mn1;

        unsigned ph[8][2];
        float sum0 = 0.0f, sum1 = 0.0f;
        #pragma unroll
        for (int nt = 0; nt < 8; nt++) {
            float p0 = __expf(s[nt][0] - mn0);
            float p1 = __expf(s[nt][1] - mn0);
            float p2 = __expf(s[nt][2] - mn1);
            float p3 = __expf(s[nt][3] - mn1);
            sum0 += p0 + p1;
            sum1 += p2 + p3;
            ph[nt][0] = packh2(p0, p1);
            ph[nt][1] = packh2(p2, p3);
        }
        sum0 += __shfl_xor_sync(0xffffffffu, sum0, 1);
        sum0 += __shfl_xor_sync(0xffffffffu, sum0, 2);
        sum1 += __shfl_xor_sync(0xffffffffu, sum1, 1);
        sum1 += __shfl_xor_sync(0xffffffffu, sum1, 2);
        lrow0 = lrow0 * f0 + sum0;
        lrow1 = lrow1 * f1 + sum1;

        #pragma unroll
        for (int nt = 0; nt < 8; nt++) {
            o[nt][0] *= f0; o[nt][1] *= f0;
            o[nt][2] *= f1; o[nt][3] *= f1;
        }

        // O += P V
        #pragma unroll
        for (int kb = 0; kb < 4; kb++) {
            const int k0i = kb * 16;
            const unsigned a0 = ph[2 * kb][0];
            const unsigned a1 = ph[2 * kb][1];
            const unsigned a2 = ph[2 * kb + 1][0];
            const unsigned a3 = ph[2 * kb + 1][1];
            #pragma unroll
            for (int dtp = 0; dtp < 4; dtp++) {
                const int d0 = dtp * 16;
                unsigned v0a, v1a, v0b, v1b;
                ldsm_x4t(v0a, v1a, v0b, v1b, sptr(&Vs[buf][k0i + vRow][d0 + vCol]));
                mma_f16(o[2 * dtp],     a0, a1, a2, a3, v0a, v1a);
                mma_f16(o[2 * dtp + 1], a0, a1, a2, a3, v0b, v1b);
            }
        }

        buf  = (buf  + 1 == FS) ? 0 : buf + 1;
        wbuf = (wbuf + 1 == FS) ? 0 : wbuf + 1;
    }

    const float inv0 = 1.0f / lrow0;
    const float inv1 = 1.0f / lrow1;
    #pragma unroll
    for (int nt = 0; nt < 8; nt++) {
        const int c = nt * 8 + 2 * tig;
        *(__half2*)&O[qbase + (size_t)(q0 + g) * DM + c] =
            __floats2half2_rn(o[nt][0] * inv0, o[nt][1] * inv0);
        *(__half2*)&O[qbase + (size_t)(q0 + g + 8) * DM + c] =
            __floats2half2_rn(o[nt][2] * inv1, o[nt][3] * inv1);
    }
}

// ---------------------------------------------------------------------------
extern "C" void kernel_launch(void* const* d_in, const int* in_sizes, int n_in,
                              void* d_out, int out_size) {
    const float* q  = (const float*)d_in[0];
    const float* k  = (const float*)d_in[1];
    const float* v  = (const float*)d_in[2];
    const float* Wq = (const float*)d_in[3];
    const float* Wk = (const float*)d_in[4];
    const float* Wv = (const float*)d_in[5];
    const float* Wo = (const float*)d_in[6];
    float* out = (float*)d_out;

    __half *qi, *ki, *vi, *Wqt, *Wkt, *Wvt, *Wot, *Qh, *Kh, *Vh, *Ch;
    cudaGetSymbolAddress((void**)&qi,  g_qi);
    cudaGetSymbolAddress((void**)&ki,  g_ki);
    cudaGetSymbolAddress((void**)&vi,  g_vi);
    cudaGetSymbolAddress((void**)&Wqt, g_Wqt);
    cudaGetSymbolAddress((void**)&Wkt, g_Wkt);
    cudaGetSymbolAddress((void**)&Wvt, g_Wvt);
    cudaGetSymbolAddress((void**)&Wot, g_Wot);
    cudaGetSymbolAddress((void**)&Qh,  g_Qh);
    cudaGetSymbolAddress((void**)&Kh,  g_Kh);
    cudaGetSymbolAddress((void**)&Vh,  g_Vh);
    cudaGetSymbolAddress((void**)&Ch,  g_Ch);

    const int gemm_smem  = GS * 2 * 128 * 40 * (int)sizeof(__half);   // 61440
    const int flash_smem = FS * 2 * 64 * 72 * (int)sizeof(__half);    // 55296
    cudaFuncSetAttribute(gemm_f16<0>, cudaFuncAttributeMaxDynamicSharedMemorySize, gemm_smem);
    cudaFuncSetAttribute(gemm_f16<1>, cudaFuncAttributeMaxDynamicSharedMemorySize, gemm_smem);
    cudaFuncSetAttribute(gemm_f16<2>, cudaFuncAttributeMaxDynamicSharedMemorySize, gemm_smem);
    cudaFuncSetAttribute(gemm_f16<3>, cudaFuncAttributeMaxDynamicSharedMemorySize, gemm_smem);
    cudaFuncSetAttribute(flash_f16,   cudaFuncAttributeMaxDynamicSharedMemorySize, flash_smem);

    const int n8 = MTOT * DM / 8;
    dim3 cGrid((n8 + 255) / 256, 3);
    cvt3_f2h<<<cGrid, 256>>>(q, k, v, qi, ki, vi, n8);
    dim3 wGrid(DM / 32, DM / 32), wThr(32, 8);
    cvt_wT<<<wGrid, wThr>>>(Wq, Wqt);
    cvt_wT<<<wGrid, wThr>>>(Wk, Wkt);
    cvt_wT<<<wGrid, wThr>>>(Wv, Wvt);
    cvt_wT<<<wGrid, wThr>>>(Wo, Wot);

    dim3 gGrid(DM / 128, MTOT / 128);

    gemm_f16<1><<<gGrid, 256, gemm_smem>>>(qi, Wqt, Qh);
    gemm_f16<2><<<gGrid, 256, gemm_smem>>>(ki, Wkt, Kh);
    gemm_f16<3><<<gGrid, 256, gemm_smem>>>(vi, Wvt, Vh);

    dim3 aGrid(SS / 128, NH, BB);
    flash_f16<<<aGrid, 256, flash_smem>>>(Qh, Kh, Vh, Ch);

    gemm_f16<0><<<gGrid, 256, gemm_smem>>>(Ch, Wot, out);
}

// round 11
// speedup vs baseline: 2.7447x; 1.1571x over previous
#include <cuda_runtime.h>
#include <cuda_fp16.h>
#include <math.h>

#define BB 4
#define SS 2048
#define DM 1024
#define NH 16
#define DK 64
#define MTOT (BB*SS)

// scratch (device globals; allocation-free at launch time)
__device__ __half g_qi[(size_t)MTOT*DM];
__device__ __half g_ki[(size_t)MTOT*DM];
__device__ __half g_vi[(size_t)MTOT*DM];
__device__ __half g_Wqt[(size_t)DM*DM];
__device__ __half g_Wkt[(size_t)DM*DM];
__device__ __half g_Wvt[(size_t)DM*DM];
__device__ __half g_Wot[(size_t)DM*DM];
__device__ __half g_Qh[(size_t)MTOT*DM];
__device__ __half g_Kh[(size_t)MTOT*DM];
__device__ __half g_Vh[(size_t)MTOT*DM];
__device__ __half g_Ch[(size_t)MTOT*DM];

// ---------------------------------------------------------------------------
// helpers
// ---------------------------------------------------------------------------
__device__ __forceinline__ void mma_f16(float c[4],
                                        unsigned a0, unsigned a1, unsigned a2, unsigned a3,
                                        unsigned b0, unsigned b1) {
    asm volatile(
        "mma.sync.aligned.m16n8k16.row.col.f32.f16.f16.f32 "
        "{%0,%1,%2,%3},{%4,%5,%6,%7},{%8,%9},{%0,%1,%2,%3};"
        : "+f"(c[0]), "+f"(c[1]), "+f"(c[2]), "+f"(c[3])
        : "r"(a0), "r"(a1), "r"(a2), "r"(a3), "r"(b0), "r"(b1));
}

__device__ __forceinline__ unsigned sptr(const void* p) {
    return (unsigned)__cvta_generic_to_shared(p);
}

__device__ __forceinline__ void ldsm_x4(unsigned& r0, unsigned& r1,
                                        unsigned& r2, unsigned& r3, unsigned a) {
    asm volatile("ldmatrix.sync.aligned.m8n8.x4.shared.b16 {%0,%1,%2,%3}, [%4];"
                 : "=r"(r0), "=r"(r1), "=r"(r2), "=r"(r3) : "r"(a));
}

__device__ __forceinline__ void ldsm_x4t(unsigned& r0, unsigned& r1,
                                         unsigned& r2, unsigned& r3, unsigned a) {
    asm volatile("ldmatrix.sync.aligned.m8n8.x4.trans.shared.b16 {%0,%1,%2,%3}, [%4];"
                 : "=r"(r0), "=r"(r1), "=r"(r2), "=r"(r3) : "r"(a));
}

__device__ __forceinline__ unsigned packh2(float a, float b) {
    __half2 h = __floats2half2_rn(a, b);
    return *(unsigned*)&h;
}

__device__ __forceinline__ float ex2f(float x) {
    float y;
    asm("ex2.approx.ftz.f32 %0, %1;" : "=f"(y) : "f"(x));
    return y;
}

__device__ __forceinline__ void cp16(void* dst_smem, const void* src_gmem) {
    unsigned s = (unsigned)__cvta_generic_to_shared(dst_smem);
    asm volatile("cp.async.cg.shared.global [%0], [%1], 16;" :: "r"(s), "l"(src_gmem));
}
__device__ __forceinline__ void cp_commit() { asm volatile("cp.async.commit_group;"); }
template<int N> __device__ __forceinline__ void cp_wait() {
    asm volatile("cp.async.wait_group %0;" :: "n"(N));
}

// log2(10000)/32, log2(e)
#define ROPE_L2 0.41524101186f
#define LOG2E   1.44269504089f

// ---------------------------------------------------------------------------
// converts
// ---------------------------------------------------------------------------
__global__ void cvt3_f2h(const float* __restrict__ q, const float* __restrict__ k,
                         const float* __restrict__ v,
                         __half* __restrict__ qo, __half* __restrict__ ko,
                         __half* __restrict__ vo, int n8) {
    const float* X;
    __half* Y;
    if (blockIdx.y == 0)      { X = q; Y = qo; }
    else if (blockIdx.y == 1) { X = k; Y = ko; }
    else                      { X = v; Y = vo; }
    int i = blockIdx.x * blockDim.x + threadIdx.x;
    if (i >= n8) return;
    const float4 v0 = *(const float4*)(X + (size_t)i * 8);
    const float4 v1 = *(const float4*)(X + (size_t)i * 8 + 4);
    __half2 h[4] = {__floats2half2_rn(v0.x, v0.y), __floats2half2_rn(v0.z, v0.w),
                    __floats2half2_rn(v1.x, v1.y), __floats2half2_rn(v1.z, v1.w)};
    *(uint4*)(Y + (size_t)i * 8) = *(uint4*)h;
}

// 4 weights [K][N] fp32 -> [N][K] fp16 in one launch (z selects matrix)
__global__ void cvt_wT4(const float* __restrict__ W0, const float* __restrict__ W1,
                        const float* __restrict__ W2, const float* __restrict__ W3,
                        __half* __restrict__ T0, __half* __restrict__ T1,
                        __half* __restrict__ T2, __half* __restrict__ T3) {
    const float* W;
    __half* Wt;
    switch (blockIdx.z) {
        case 0:  W = W0; Wt = T0; break;
        case 1:  W = W1; Wt = T1; break;
        case 2:  W = W2; Wt = T2; break;
        default: W = W3; Wt = T3; break;
    }
    __shared__ float t[32][33];
    const int bn = blockIdx.x * 32, bk = blockIdx.y * 32;
    const int x = threadIdx.x, y = threadIdx.y;
    #pragma unroll
    for (int i = 0; i < 32; i += 8)
        t[y + i][x] = W[(size_t)(bk + y + i) * DM + bn + x];
    __syncthreads();
    #pragma unroll
    for (int i = 0; i < 32; i += 8)
        Wt[(size_t)(bn + y + i) * DM + bk + x] = __float2half(t[x][y + i]);
}

// ---------------------------------------------------------------------------
// GEMM core: acc = A[M,K] * Bt[N,K]^T for one 128x128 tile, 4-stage cp.async.
// 256 thr = 8 warps (4x2), warp tile 32x64, ldmatrix fragments.
// ---------------------------------------------------------------------------
#define GS 4

__device__ __forceinline__ void gemm_core(const __half* __restrict__ asrc,
                                          const __half* __restrict__ bsrc,
                                          __half (*As)[128][40], __half (*Bs)[128][40],
                                          int lr, int lc, int rw, int cw,
                                          int aRow, int aCol, int bRow, int bCol,
                                          float acc[2][8][4]) {
    #pragma unroll
    for (int p = 0; p < GS - 1; p++) {
        cp16(&As[p][lr][lc],     asrc + p * 32);
        cp16(&As[p][lr][lc + 8], asrc + p * 32 + 8);
        cp16(&Bs[p][lr][lc],     bsrc + p * 32);
        cp16(&Bs[p][lr][lc + 8], bsrc + p * 32 + 8);
        cp_commit();
    }

    const int NT = DM / 32;
    int buf = 0, wbuf = GS - 1;
    for (int t = 0; t < NT; t++) {
        cp_wait<GS - 2>();
        __syncthreads();

        if (t + GS - 1 < NT) {
            const __half* a2 = asrc + (t + GS - 1) * 32;
            const __half* b2 = bsrc + (t + GS - 1) * 32;
            cp16(&As[wbuf][lr][lc],     a2);
            cp16(&As[wbuf][lr][lc + 8], a2 + 8);
            cp16(&Bs[wbuf][lr][lc],     b2);
            cp16(&Bs[wbuf][lr][lc + 8], b2 + 8);
        }
        cp_commit();

        #pragma unroll
        for (int kb = 0; kb < 2; kb++) {
            const int kk = kb * 16;
            unsigned a[2][4];
            #pragma unroll
            for (int mt = 0; mt < 2; mt++) {
                const int r = rw * 32 + mt * 16;
                ldsm_x4(a[mt][0], a[mt][1], a[mt][2], a[mt][3],
                        sptr(&As[buf][r + aRow][kk + aCol]));
            }
            unsigned b[8][2];
            #pragma unroll
            for (int ntp = 0; ntp < 4; ntp++) {
                const int n0 = cw * 64 + ntp * 16;
                ldsm_x4(b[2 * ntp][0], b[2 * ntp][1], b[2 * ntp + 1][0], b[2 * ntp + 1][1],
                        sptr(&Bs[buf][n0 + bRow][kk + bCol]));
            }
            #pragma unroll
            for (int mt = 0; mt < 2; mt++)
                #pragma unroll
                for (int nt = 0; nt < 8; nt++)
                    mma_f16(acc[mt][nt], a[mt][0], a[mt][1], a[mt][2], a[mt][3],
                            b[nt][0], b[nt][1]);
        }
        buf  = (buf  + 1 == GS) ? 0 : buf + 1;
        wbuf = (wbuf + 1 == GS) ? 0 : wbuf + 1;
    }
}

// ---------------------------------------------------------------------------
// Fused Q/K/V projection: blockIdx.z selects input/weight/output + epilogue.
// z=0: Q (rope + 0.125*log2e scale), z=1: K (rope), z=2: V (plain). half out.
// ---------------------------------------------------------------------------
__global__ __launch_bounds__(256) void gemm_qkv(
        const __half* __restrict__ qi, const __half* __restrict__ ki,
        const __half* __restrict__ vi,
        const __half* __restrict__ Wqt, const __half* __restrict__ Wkt,
        const __half* __restrict__ Wvt,
        __half* __restrict__ Qh, __half* __restrict__ Kh, __half* __restrict__ Vh) {
    extern __shared__ __half gsm[];
    __half (*As)[128][40] = (__half(*)[128][40])gsm;
    __half (*Bs)[128][40] = (__half(*)[128][40])(gsm + GS * 128 * 40);

    const __half *A, *Bt;
    __half* C;
    const int mode = blockIdx.z;
    if (mode == 0)      { A = qi; Bt = Wqt; C = Qh; }
    else if (mode == 1) { A = ki; Bt = Wkt; C = Kh; }
    else                { A = vi; Bt = Wvt; C = Vh; }

    const int tid  = threadIdx.x;
    const int wid  = tid >> 5;
    const int lane = tid & 31;
    const int g    = lane >> 2;
    const int tig  = lane & 3;
    const int rw   = wid >> 1;
    const int cw   = wid & 1;
    const int m0   = blockIdx.y * 128;
    const int n0b  = blockIdx.x * 128;

    const int lr = tid >> 1;
    const int lc = (tid & 1) * 16;
    const int aRow = lane & 15;
    const int aCol = 8 * (lane >> 4);
    const int bRow = 8 * (lane >> 4) + (lane & 7);
    const int bCol = 8 * ((lane >> 3) & 1);

    float acc[2][8][4];
    #pragma unroll
    for (int i = 0; i < 2; i++)
        #pragma unroll
        for (int j = 0; j < 8; j++)
            #pragma unroll
            for (int l = 0; l < 4; l++) acc[i][j][l] = 0.0f;

    gemm_core(A + (size_t)(m0 + lr) * DM + lc, Bt + (size_t)(n0b + lr) * DM + lc,
              As, Bs, lr, lc, rw, cw, aRow, aCol, bRow, bCol, acc);

    const float qscale = 0.125f * LOG2E;
    #pragma unroll
    for (int mt = 0; mt < 2; mt++) {
        const int r = m0 + rw * 32 + mt * 16 + g;
        const int pos0 = r & (SS - 1);
        const int pos8 = (r + 8) & (SS - 1);
        #pragma unroll
        for (int nt = 0; nt < 8; nt++) {
            const int c = n0b + cw * 64 + nt * 8 + 2 * tig;
            float y0 = acc[mt][nt][0], y1 = acc[mt][nt][1];
            float y2 = acc[mt][nt][2], y3 = acc[mt][nt][3];
            if (mode < 2) {
                const int i = (c & 63) >> 1;
                const float inv = exp2f(-(float)i * ROPE_L2);
                float s0, c0, s8, c8;
                sincosf((float)pos0 * inv, &s0, &c0);
                sincosf((float)pos8 * inv, &s8, &c8);
                float x1 = y0, x2 = y1;
                y0 = x1 * c0 - x2 * s0;
                y1 = x1 * s0 + x2 * c0;
                x1 = y2; x2 = y3;
                y2 = x1 * c8 - x2 * s8;
                y3 = x1 * s8 + x2 * c8;
                if (mode == 0) { y0 *= qscale; y1 *= qscale; y2 *= qscale; y3 *= qscale; }
            }
            *(__half2*)&C[(size_t)r * DM + c]       = __floats2half2_rn(y0, y1);
            *(__half2*)&C[(size_t)(r + 8) * DM + c] = __floats2half2_rn(y2, y3);
        }
    }
}

// ---------------------------------------------------------------------------
// Output projection: fp32 store.
// ---------------------------------------------------------------------------
__global__ __launch_bounds__(256) void gemm_wo(const __half* __restrict__ A,
                                               const __half* __restrict__ Bt,
                                               float* __restrict__ C) {
    extern __shared__ __half gsm[];
    __half (*As)[128][40] = (__half(*)[128][40])gsm;
    __half (*Bs)[128][40] = (__half(*)[128][40])(gsm + GS * 128 * 40);

    const int tid  = threadIdx.x;
    const int wid  = tid >> 5;
    const int lane = tid & 31;
    const int g    = lane >> 2;
    const int tig  = lane & 3;
    const int rw   = wid >> 1;
    const int cw   = wid & 1;
    const int m0   = blockIdx.y * 128;
    const int n0b  = blockIdx.x * 128;

    const int lr = tid >> 1;
    const int lc = (tid & 1) * 16;
    const int aRow = lane & 15;
    const int aCol = 8 * (lane >> 4);
    const int bRow = 8 * (lane >> 4) + (lane & 7);
    const int bCol = 8 * ((lane >> 3) & 1);

    float acc[2][8][4];
    #pragma unroll
    for (int i = 0; i < 2; i++)
        #pragma unroll
        for (int j = 0; j < 8; j++)
            #pragma unroll
            for (int l = 0; l < 4; l++) acc[i][j][l] = 0.0f;

    gemm_core(A + (size_t)(m0 + lr) * DM + lc, Bt + (size_t)(n0b + lr) * DM + lc,
              As, Bs, lr, lc, rw, cw, aRow, aCol, bRow, bCol, acc);

    #pragma unroll
    for (int mt = 0; mt < 2; mt++) {
        const int r = m0 + rw * 32 + mt * 16 + g;
        #pragma unroll
        for (int nt = 0; nt < 8; nt++) {
            const int c = n0b + cw * 64 + nt * 8 + 2 * tig;
            *(float2*)&C[(size_t)r * DM + c] =
                make_float2(acc[mt][nt][0], acc[mt][nt][1]);
            *(float2*)&C[(size_t)(r + 8) * DM + c] =
                make_float2(acc[mt][nt][2], acc[mt][nt][3]);
        }
    }
}

// ---------------------------------------------------------------------------
// Flash attention, fp16 MMA + ldmatrix, 4-stage cp.async, 1 sync/iter.
// Softmax in log2 domain (Q pre-scaled by 0.125*log2e) -> raw ex2.
// ---------------------------------------------------------------------------
#define FS 4
__global__ __launch_bounds__(256, 2) void flash_f16(const __half* __restrict__ Qh,
                                                    const __half* __restrict__ Kh,
                                                    const __half* __restrict__ Vh,
                                                    __half* __restrict__ O) {
    extern __shared__ __half fsm[];
    __half (*Ks)[64][72] = (__half(*)[64][72])fsm;
    __half (*Vs)[64][72] = (__half(*)[64][72])(fsm + FS * 64 * 72);

    const int tid  = threadIdx.x;
    const int wid  = tid >> 5;
    const int lane = tid & 31;
    const int g    = lane >> 2;
    const int tig  = lane & 3;
    const int h    = blockIdx.y;
    const int b    = blockIdx.z;
    const int q0   = wid * 16;
    const size_t qbase = ((size_t)b * SS + blockIdx.x * 128) * DM + h * DK;
    const size_t kvbase = (size_t)b * SS * DM + h * DK;

    const int bRow = 8 * (lane >> 4) + (lane & 7);
    const int bCol = 8 * ((lane >> 3) & 1);
    const int vRow = lane & 15;
    const int vCol = 8 * (lane >> 4);

    unsigned qf[4][4];
    {
        const __half* q_r0 = Qh + qbase + (size_t)(q0 + g) * DM;
        const __half* q_r8 = Qh + qbase + (size_t)(q0 + g + 8) * DM;
        #pragma unroll
        for (int kb = 0; kb < 4; kb++) {
            const int cc = kb * 16 + 2 * tig;
            qf[kb][0] = *(const unsigned*)(q_r0 + cc);
            qf[kb][1] = *(const unsigned*)(q_r8 + cc);
            qf[kb][2] = *(const unsigned*)(q_r0 + cc + 8);
            qf[kb][3] = *(const unsigned*)(q_r8 + cc + 8);
        }
    }

    const int pr = tid >> 2;
    const int pc = (tid & 3) * 16;
    auto kv_issue = [&](int kt, int buf) {
        const __half* ksrc = Kh + kvbase + ((size_t)kt * 64 + pr) * DM + pc;
        const __half* vsrc = Vh + kvbase + ((size_t)kt * 64 + pr) * DM + pc;
        cp16(&Ks[buf][pr][pc],     ksrc);
        cp16(&Ks[buf][pr][pc + 8], ksrc + 8);
        cp16(&Vs[buf][pr][pc],     vsrc);
        cp16(&Vs[buf][pr][pc + 8], vsrc + 8);
    };

    #pragma unroll
    for (int p = 0; p < FS - 1; p++) { kv_issue(p, p); cp_commit(); }

    float o[8][4];
    #pragma unroll
    for (int nt = 0; nt < 8; nt++)
        #pragma unroll
        for (int j = 0; j < 4; j++) o[nt][j] = 0.0f;
    float mrow0 = -INFINITY, mrow1 = -INFINITY;
    float lrow0 = 0.0f, lrow1 = 0.0f;

    const int NKT = SS / 64;
    int buf = 0, wbuf = FS - 1;
    for (int kt = 0; kt < NKT; kt++) {
        cp_wait<FS - 2>();
        __syncthreads();

        if (kt + FS - 1 < NKT) kv_issue(kt + FS - 1, wbuf);
        cp_commit();

        // S (log2 domain)
        float s[8][4];
        #pragma unroll
        for (int nt = 0; nt < 8; nt++)
            #pragma unroll
            for (int j = 0; j < 4; j++) s[nt][j] = 0.0f;

        #pragma unroll
        for (int kb = 0; kb < 4; kb++) {
            const int kk = kb * 16;
            #pragma unroll
            for (int ntp = 0; ntp < 4; ntp++) {
                const int n0 = ntp * 16;
                unsigned b0a, b1a, b0b, b1b;
                ldsm_x4(b0a, b1a, b0b, b1b, sptr(&Ks[buf][n0 + bRow][kk + bCol]));
                mma_f16(s[2 * ntp],     qf[kb][0], qf[kb][1], qf[kb][2], qf[kb][3], b0a, b1a);
                mma_f16(s[2 * ntp + 1], qf[kb][0], qf[kb][1], qf[kb][2], qf[kb][3], b0b, b1b);
            }
        }

        // online softmax in log2 domain
        float mx0 = -INFINITY, mx1 = -INFINITY;
        #pragma unroll
        for (int nt = 0; nt < 8; nt++) {
            mx0 = fmaxf(mx0, fmaxf(s[nt][0], s[nt][1]));
            mx1 = fmaxf(mx1, fmaxf(s[nt][2], s[nt][3]));
        }
        mx0 = fmaxf(mx0, __shfl_xor_sync(0xffffffffu, mx0, 1));
        mx0 = fmaxf(mx0, __shfl_xor_sync(0xffffffffu, mx0, 2));
        mx1 = fmaxf(mx1, __shfl_xor_sync(0xffffffffu, mx1, 1));
        mx1 = fmaxf(mx1, __shfl_xor_sync(0xffffffffu, mx1, 2));

        const float mn0 = fmaxf(mrow0, mx0);
        const float mn1 = fmaxf(mrow1, mx1);
        const float f0 = ex2f(mrow0 - mn0);
        const float f1 = ex2f(mrow1 - mn1);
        mrow0 = mn0; mrow1 = mn1;

        unsigned ph[8][2];
        float sum0 = 0.0f, sum1 = 0.0f;
        #pragma unroll
        for (int nt = 0; nt < 8; nt++) {
            float p0 = ex2f(s[nt][0] - mn0);
            float p1 = ex2f(s[nt][1] - mn0);
            float p2 = ex2f(s[nt][2] - mn1);
            float p3 = ex2f(s[nt][3] - mn1);
            sum0 += p0 + p1;
            sum1 += p2 + p3;
            ph[nt][0] = packh2(p0, p1);
            ph[nt][1] = packh2(p2, p3);
        }
        sum0 += __shfl_xor_sync(0xffffffffu, sum0, 1);
        sum0 += __shfl_xor_sync(0xffffffffu, sum0, 2);
        sum1 += __shfl_xor_sync(0xffffffffu, sum1, 1);
        sum1 += __shfl_xor_sync(0xffffffffu, sum1, 2);
        lrow0 = lrow0 * f0 + sum0;
        lrow1 = lrow1 * f1 + sum1;

        #pragma unroll
        for (int nt = 0; nt < 8; nt++) {
            o[nt][0] *= f0; o[nt][1] *= f0;
            o[nt][2] *= f1; o[nt][3] *= f1;
        }

        // O += P V
        #pragma unroll
        for (int kb = 0; kb < 4; kb++) {
            const int k0i = kb * 16;
            const unsigned a0 = ph[2 * kb][0];
            const unsigned a1 = ph[2 * kb][1];
            const unsigned a2 = ph[2 * kb + 1][0];
            const unsigned a3 = ph[2 * kb + 1][1];
            #pragma unroll
            for (int dtp = 0; dtp < 4; dtp++) {
                const int d0 = dtp * 16;
                unsigned v0a, v1a, v0b, v1b;
                ldsm_x4t(v0a, v1a, v0b, v1b, sptr(&Vs[buf][k0i + vRow][d0 + vCol]));
                mma_f16(o[2 * dtp],     a0, a1, a2, a3, v0a, v1a);
                mma_f16(o[2 * dtp + 1], a0, a1, a2, a3, v0b, v1b);
            }
        }

        buf  = (buf  + 1 == FS) ? 0 : buf + 1;
        wbuf = (wbuf + 1 == FS) ? 0 : wbuf + 1;
    }

    const float inv0 = 1.0f / lrow0;
    const float inv1 = 1.0f / lrow1;
    #pragma unroll
    for (int nt = 0; nt < 8; nt++) {
        const int c = nt * 8 + 2 * tig;
        *(__half2*)&O[qbase + (size_t)(q0 + g) * DM + c] =
            __floats2half2_rn(o[nt][0] * inv0, o[nt][1] * inv0);
        *(__half2*)&O[qbase + (size_t)(q0 + g + 8) * DM + c] =
            __floats2half2_rn(o[nt][2] * inv1, o[nt][3] * inv1);
    }
}

// ---------------------------------------------------------------------------
extern "C" void kernel_launch(void* const* d_in, const int* in_sizes, int n_in,
                              void* d_out, int out_size) {
    const float* q  = (const float*)d_in[0];
    const float* k  = (const float*)d_in[1];
    const float* v  = (const float*)d_in[2];
    const float* Wq = (const float*)d_in[3];
    const float* Wk = (const float*)d_in[4];
    const float* Wv = (const float*)d_in[5];
    const float* Wo = (const float*)d_in[6];
    float* out = (float*)d_out;

    __half *qi, *ki, *vi, *Wqt, *Wkt, *Wvt, *Wot, *Qh, *Kh, *Vh, *Ch;
    cudaGetSymbolAddress((void**)&qi,  g_qi);
    cudaGetSymbolAddress((void**)&ki,  g_ki);
    cudaGetSymbolAddress((void**)&vi,  g_vi);
    cudaGetSymbolAddress((void**)&Wqt, g_Wqt);
    cudaGetSymbolAddress((void**)&Wkt, g_Wkt);
    cudaGetSymbolAddress((void**)&Wvt, g_Wvt);
    cudaGetSymbolAddress((void**)&Wot, g_Wot);
    cudaGetSymbolAddress((void**)&Qh,  g_Qh);
    cudaGetSymbolAddress((void**)&Kh,  g_Kh);
    cudaGetSymbolAddress((void**)&Vh,  g_Vh);
    cudaGetSymbolAddress((void**)&Ch,  g_Ch);

    const int gemm_smem  = GS * 2 * 128 * 40 * (int)sizeof(__half);   // 81920
    const int flash_smem = FS * 2 * 64 * 72 * (int)sizeof(__half);    // 73728
    cudaFuncSetAttribute(gemm_qkv, cudaFuncAttributeMaxDynamicSharedMemorySize, gemm_smem);
    cudaFuncSetAttribute(gemm_wo,  cudaFuncAttributeMaxDynamicSharedMemorySize, gemm_smem);
    cudaFuncSetAttribute(flash_f16, cudaFuncAttributeMaxDynamicSharedMemorySize, flash_smem);

    const int n8 = MTOT * DM / 8;
    dim3 cGrid((n8 + 255) / 256, 3);
    cvt3_f2h<<<cGrid, 256>>>(q, k, v, qi, ki, vi, n8);
    dim3 wGrid(DM / 32, DM / 32, 4), wThr(32, 8);
    cvt_wT4<<<wGrid, wThr>>>(Wq, Wk, Wv, Wo, Wqt, Wkt, Wvt, Wot);

    // fused Q/K/V projections (one launch, 1536 CTAs)
    dim3 pGrid(DM / 128, MTOT / 128, 3);
    gemm_qkv<<<pGrid, 256, gemm_smem>>>(qi, ki, vi, Wqt, Wkt, Wvt, Qh, Kh, Vh);

    // flash attention
    dim3 aGrid(SS / 128, NH, BB);
    flash_f16<<<aGrid, 256, flash_smem>>>(Qh, Kh, Vh, Ch);

    // output projection
    dim3 oGrid(DM / 128, MTOT / 128);
    gemm_wo<<<oGrid, 256, gemm_smem>>>(Ch, Wot, out);
}